// round 10
// baseline (speedup 1.0000x reference)
#include <cuda_runtime.h>
#include <cuda_bf16.h>
#include <cstdint>

// HarmonicAwaredAttention via warp-level HMMA (mma.sync, arch-agnostic PTX).
// R10: fused K+V GEMM over a single A-fragment stream (A-LDSM halved for K/V);
//      ev[] removed from softmax (recompute exp); 512 threads, grid 4(M)x4(N).
// GEMMs: m16n8k16 bf16 MMA, fp32 emulated with bf16 hi/lo 3-term split.

#define TT 512
#define NTHREADS 512
#define LDH_B  272            // bf16 row stride in bytes (136 elems)
#define LDKV   144            // fp32 row stride (floats) for K/V, skewed
#define LDQ    132            // fp32 row stride (floats) for Q overlay

// smem byte offsets
#define HHI_OFF 0
#define HLO_OFF 34816
#define QS_OFF  0              // fp32 Q overlays H region (sequenced by syncs)
#define KS_OFF  69632
#define VS_OFF  143360
#define SMEM_TOTAL 217088

// weights, fragment-linear uint4: [gemm][ks 0..7][j 0..15][lane 0..31]
// uint4 = {bh.x, bh.y, bl.x, bl.y}
__device__ __align__(16) uint4 g_wfrag[16 * 4096];
__device__ float g_pe[128 * 128];     // g_pe[c*128 + f]

__device__ __forceinline__ uint32_t smem_u32(const void* p) {
    uint32_t a;
    asm("{ .reg .u64 t; cvta.to.shared.u64 t, %1; cvt.u32.u64 %0, t; }" : "=r"(a) : "l"(p));
    return a;
}

#define LDSM(r, addr) \
    asm volatile("ldmatrix.sync.aligned.m8n8.x4.shared.b16 {%0,%1,%2,%3}, [%4];" \
        : "=r"((r)[0]), "=r"((r)[1]), "=r"((r)[2]), "=r"((r)[3]) : "r"(addr))

#define MMA(dp, a, bx, by) \
    asm volatile("mma.sync.aligned.m16n8k16.row.col.f32.bf16.bf16.f32 " \
        "{%0,%1,%2,%3},{%4,%5,%6,%7},{%8,%9},{%0,%1,%2,%3};" \
        : "+f"((dp)[0]), "+f"((dp)[1]), "+f"((dp)[2]), "+f"((dp)[3]) \
        : "r"((a)[0]), "r"((a)[1]), "r"((a)[2]), "r"((a)[3]), "r"(bx), "r"(by))

// ---------------- prologue: fragment-pack weights + PE table ----------------
// gemm g = 4*layer + {0:Wk,1:Wv,2:Wq,3:Wo}.  B[n][k] = W[k][n].
// entry e: lane=e&31, j=(e>>5)&15 (n-tile), ks=e>>9.
// lane fragment: n = 8j + (lane>>2); k0 = 16ks + 2(lane&3).
__global__ void prep_w(const float* __restrict__ Wq, const float* __restrict__ Wk,
                       const float* __restrict__ Wv, const float* __restrict__ Wo)
{
    int g = blockIdx.x;
    if (g == 16) {   // PE table
        for (int idx = threadIdx.x; idx < 128 * 128; idx += blockDim.x) {
            int c = idx >> 7, f = idx & 127;
            float e     = (float)(c & ~1) * (1.0f / 128.0f);
            float denom = exp2f(e * 13.287712379549449f);   // 10000^(i/128)
            float ang   = (float)f / denom;
            g_pe[c * 128 + f] = (c & 1) ? cosf(ang) : sinf(ang);
        }
        return;
    }
    int l = g >> 2, m = g & 3;
    const float* src = (m == 0 ? Wk : m == 1 ? Wv : m == 2 ? Wq : Wo) + l * 16384;
    for (int e = threadIdx.x; e < 4096; e += blockDim.x) {
        int lane = e & 31, j = (e >> 5) & 15, ks = e >> 9;
        int n  = 8 * j + (lane >> 2);
        int k0 = 16 * ks + 2 * (lane & 3);
        float w00 = src[k0 * 128 + n],       w01 = src[(k0 + 1) * 128 + n];
        float w10 = src[(k0 + 8) * 128 + n], w11 = src[(k0 + 9) * 128 + n];
        __nv_bfloat162 h0 = __floats2bfloat162_rn(w00, w01);
        __nv_bfloat162 h1 = __floats2bfloat162_rn(w10, w11);
        float2 f0 = __bfloat1622float2(h0), f1 = __bfloat1622float2(h1);
        __nv_bfloat162 l0 = __floats2bfloat162_rn(w00 - f0.x, w01 - f0.y);
        __nv_bfloat162 l1 = __floats2bfloat162_rn(w10 - f1.x, w11 - f1.y);
        uint4 o;
        o.x = *(uint32_t*)&h0;  o.y = *(uint32_t*)&h1;
        o.z = *(uint32_t*)&l0;  o.w = *(uint32_t*)&l1;
        g_wfrag[g * 4096 + e] = o;
    }
}

// ------- fused K+V GEMM: warp (mw,nw) computes two D[32x32] tiles -------
// One A-fragment stream (LDSM once) feeds both projections' MMAs.
__device__ __forceinline__ void gemm_kv(uint32_t a_hi_lane, uint32_t a_lo_lane,
                                        const uint4* __restrict__ wfK,
                                        const uint4* __restrict__ wfV,
                                        int mw, float (*dK)[4], float (*dV)[4])
{
#pragma unroll
    for (int i = 0; i < 8; i++) {
        dK[i][0] = 0.f; dK[i][1] = 0.f; dK[i][2] = 0.f; dK[i][3] = 0.f;
        dV[i][0] = 0.f; dV[i][1] = 0.f; dV[i][2] = 0.f; dV[i][3] = 0.f;
    }
    const uint32_t a_row_off = (uint32_t)(mw * 32) * LDH_B;

    uint4 bk = __ldg(wfK), bv = __ldg(wfV);

#pragma unroll
    for (int ks = 0; ks < 8; ks++) {
        uint32_t ah[2][4], al[2][4];
#pragma unroll
        for (int mt = 0; mt < 2; mt++) {
            uint32_t off = a_row_off + (uint32_t)(mt * 16) * LDH_B + (uint32_t)ks * 32;
            LDSM(ah[mt], a_hi_lane + off);
            LDSM(al[mt], a_lo_lane + off);
        }
#pragma unroll
        for (int jj = 0; jj < 4; jj++) {
            // prefetch next (ks,jj) fragment (compile-time offsets; wraps at end)
            const int nks = (jj == 3) ? ((ks + 1) & 7) : ks;
            const int njj = (jj + 1) & 3;
            const int noff = nks * 512 + njj * 32;
            uint4 nbk = __ldg(wfK + noff);
            uint4 nbv = __ldg(wfV + noff);
#pragma unroll
            for (int mt = 0; mt < 2; mt++) {
                MMA(dK[mt * 4 + jj], ah[mt], bk.x, bk.y);   // Ah*Bh
                MMA(dK[mt * 4 + jj], ah[mt], bk.z, bk.w);   // Ah*Bl
                MMA(dK[mt * 4 + jj], al[mt], bk.x, bk.y);   // Al*Bh
                MMA(dV[mt * 4 + jj], ah[mt], bv.x, bv.y);
                MMA(dV[mt * 4 + jj], ah[mt], bv.z, bv.w);
                MMA(dV[mt * 4 + jj], al[mt], bv.x, bv.y);
            }
            bk = nbk; bv = nbv;
        }
    }
}

// ------------- single GEMM: warp (mw,nw) computes D[32 rows x 32 cols] -------------
__device__ __forceinline__ void gemm_mma(uint32_t a_hi_lane, uint32_t a_lo_lane,
                                         const uint4* __restrict__ wf,
                                         int mw, float (*d)[4])
{
#pragma unroll
    for (int i = 0; i < 8; i++) { d[i][0] = 0.f; d[i][1] = 0.f; d[i][2] = 0.f; d[i][3] = 0.f; }

    const uint32_t a_row_off = (uint32_t)(mw * 32) * LDH_B;
    uint4 b = __ldg(wf);

#pragma unroll
    for (int ks = 0; ks < 8; ks++) {
        uint32_t ah[2][4], al[2][4];
#pragma unroll
        for (int mt = 0; mt < 2; mt++) {
            uint32_t off = a_row_off + (uint32_t)(mt * 16) * LDH_B + (uint32_t)ks * 32;
            LDSM(ah[mt], a_hi_lane + off);
            LDSM(al[mt], a_lo_lane + off);
        }
#pragma unroll
        for (int jj = 0; jj < 4; jj++) {
            const int nks = (jj == 3) ? ((ks + 1) & 7) : ks;
            const int njj = (jj + 1) & 3;
            uint4 nb = __ldg(wf + nks * 512 + njj * 32);
#pragma unroll
            for (int mt = 0; mt < 2; mt++) {
                MMA(d[mt * 4 + jj], ah[mt], b.x, b.y);   // Ah*Bh
                MMA(d[mt * 4 + jj], ah[mt], b.z, b.w);   // Ah*Bl
                MMA(d[mt * 4 + jj], al[mt], b.x, b.y);   // Al*Bh
            }
            b = nb;
        }
    }
}

// D + bias -> fp32 smem buffer; stride ldf, column skew cs (floats).
__device__ __forceinline__ void epi_f32(float (*d)[4], float* buf, const float* bias,
                                        int mw, int nw, int lane, int ldf, int cs)
{
    int rq = lane >> 2, cq = 2 * (lane & 3);
#pragma unroll
    for (int jj = 0; jj < 4; jj++) {
        int c = 32 * nw + 8 * jj + cq;
        float b0 = __ldg(&bias[c]), b1 = __ldg(&bias[c + 1]);
#pragma unroll
        for (int mt = 0; mt < 2; mt++) {
            int r0 = 32 * mw + 16 * mt + rq;
            float2 v0 = make_float2(d[mt*4+jj][0] + b0, d[mt*4+jj][1] + b1);
            float2 v1 = make_float2(d[mt*4+jj][2] + b0, d[mt*4+jj][3] + b1);
            *(float2*)&buf[r0 * ldf + c + cs]       = v0;
            *(float2*)&buf[(r0 + 8) * ldf + c + cs] = v1;
        }
    }
}

// D + bias -> bf16 hi/lo H buffers
__device__ __forceinline__ void epi_bf16(float (*d)[4], unsigned char* sm,
                                         const float* bias, int mw, int nw, int lane)
{
    int rq = lane >> 2, cq = 2 * (lane & 3);
#pragma unroll
    for (int jj = 0; jj < 4; jj++) {
        int c = 32 * nw + 8 * jj + cq;
        float b0 = __ldg(&bias[c]), b1 = __ldg(&bias[c + 1]);
#pragma unroll
        for (int mt = 0; mt < 2; mt++) {
            int r0 = 32 * mw + 16 * mt + rq;
#pragma unroll
            for (int hh = 0; hh < 2; hh++) {
                int r = r0 + 8 * hh;
                float v0 = d[mt*4+jj][2*hh]     + b0;
                float v1 = d[mt*4+jj][2*hh + 1] + b1;
                __nv_bfloat162 hi2 = __floats2bfloat162_rn(v0, v1);
                float2 hf = __bfloat1622float2(hi2);
                __nv_bfloat162 lo2 = __floats2bfloat162_rn(v0 - hf.x, v1 - hf.y);
                *(uint32_t*)(sm + HHI_OFF + r * LDH_B + c * 2) = *(uint32_t*)&hi2;
                *(uint32_t*)(sm + HLO_OFF + r * LDH_B + c * 2) = *(uint32_t*)&lo2;
            }
        }
    }
}

// D + bias -> gmem out (transposed: out[c][r], channel stride 65536)
__device__ __forceinline__ void epi_out(float (*d)[4], float* ob, const float* bias,
                                        int mw, int nw, int lane)
{
    int rq = lane >> 2, cq = 2 * (lane & 3);
#pragma unroll
    for (int jj = 0; jj < 4; jj++) {
        int c = 32 * nw + 8 * jj + cq;
        float b0 = __ldg(&bias[c]), b1 = __ldg(&bias[c + 1]);
#pragma unroll
        for (int mt = 0; mt < 2; mt++) {
            int r0 = 32 * mw + 16 * mt + rq;
            ob[(size_t)c * 65536 + r0]           = d[mt*4+jj][0] + b0;
            ob[(size_t)(c + 1) * 65536 + r0]     = d[mt*4+jj][1] + b1;
            ob[(size_t)c * 65536 + r0 + 8]       = d[mt*4+jj][2] + b0;
            ob[(size_t)(c + 1) * 65536 + r0 + 8] = d[mt*4+jj][3] + b1;
        }
    }
}

// 32 fp32 vals (one row, one 32-col group) -> bf16 hi/lo into H buffers
__device__ __forceinline__ void stage_rowvals(const float* v, unsigned char* sm,
                                              int row, int c0)
{
#pragma unroll
    for (int i = 0; i < 16; i++) {
        float a = v[2 * i], b = v[2 * i + 1];
        __nv_bfloat162 hi2 = __floats2bfloat162_rn(a, b);
        float2 hf = __bfloat1622float2(hi2);
        __nv_bfloat162 lo2 = __floats2bfloat162_rn(a - hf.x, b - hf.y);
        *(uint32_t*)(sm + HHI_OFF + row * LDH_B + (c0 + 2 * i) * 2) = *(uint32_t*)&hi2;
        *(uint32_t*)(sm + HLO_OFF + row * LDH_B + (c0 + 2 * i) * 2) = *(uint32_t*)&lo2;
    }
}

extern __shared__ unsigned char smem[];

__global__ void __launch_bounds__(NTHREADS, 1)
hattn_mma(const float* __restrict__ x,
          const float* __restrict__ bq, const float* __restrict__ bk,
          const float* __restrict__ bv, const float* __restrict__ bo,
          float* __restrict__ out)
{
    const int tid = threadIdx.x;
    const int w = tid >> 5, lane = tid & 31;
    const int mw = w & 3, nw = w >> 2;          // warp grid 4(M) x 4(N)
    const int bi = blockIdx.x / TT;
    const int t  = blockIdx.x % TT;

    float* Qs = (float*)(smem + QS_OFF);
    float* Ks = (float*)(smem + KS_OFF);
    float* Vs = (float*)(smem + VS_OFF);

    const uint32_t smbase = smem_u32(smem);
    const uint32_t a_hi_lane = smbase + HHI_OFF + (lane & 15) * LDH_B + (lane >> 4) * 16;
    const uint32_t a_lo_lane = smbase + HLO_OFF + (lane & 15) * LDH_B + (lane >> 4) * 16;

    const int wfoff = (4 * nw) * 32 + lane;     // B fragment base offset for this warp

    // attention / staging mapping: thread owns (row, 32-col group qg)
    const int row = tid >> 2;
    const int qg  = tid & 3;                    // head = qg>>1, half = qg&1
    const int c0  = 32 * qg;
    const int kvs = c0 + 4 * qg;                // skewed col offset into Ks/Vs

    // ---- stage H = x + PE ----
    {
        const float* xb = x + (size_t)bi * 8388608 + (size_t)t * 128;
        float v[32];
#pragma unroll
        for (int c = 0; c < 32; c++)
            v[c] = xb[(size_t)(c0 + c) * 65536 + row] + g_pe[(c0 + c) * 128 + row];
        stage_rowvals(v, smem, row, c0);
    }

    const int deltas[11] = {-124, -111, -96, -76, -48, 0, 48, 76, 96, 111, 124};
    float dK[8][4], dV[8][4];

#pragma unroll 1
    for (int l = 0; l < 4; l++) {
        __syncthreads();                                     // H staged/visible

        gemm_kv(a_hi_lane, a_lo_lane,
                g_wfrag + (4*l + 0) * 4096 + wfoff,
                g_wfrag + (4*l + 1) * 4096 + wfoff, mw, dK, dV);
        epi_f32(dK, Ks, bk + l * 128, mw, nw, lane, LDKV, 4 * nw);
        epi_f32(dV, Vs, bv + l * 128, mw, nw, lane, LDKV, 4 * nw);
        gemm_mma(a_hi_lane, a_lo_lane, g_wfrag + (4*l + 2) * 4096 + wfoff, mw, dK);
        __syncthreads();                                     // all H reads done
        epi_f32(dK, Qs, bq + l * 128, mw, nw, lane, LDQ, 0); // Q overlays H region
        __syncthreads();                                     // Q/K/V visible

        // ---- sparse harmonic attention: thread owns (row, qg) ----
        float o[32];
        {
            float q[32];
            const float* qp = &Qs[row * LDQ + c0];
#pragma unroll
            for (int i = 0; i < 32; i++) q[i] = qp[i];

            float sv[11];
#pragma unroll
            for (int dd = 0; dd < 11; dd++) {
                int j = row + deltas[dd];
                float s = -1e30f;
                if ((unsigned)j < 128u) {
                    const float* kp = &Ks[j * LDKV + kvs];
                    float a = 0.f;
#pragma unroll
                    for (int i = 0; i < 8; i++) {
                        float4 kk = *(const float4*)&kp[i * 4];
                        a = fmaf(q[4*i],   kk.x, a);
                        a = fmaf(q[4*i+1], kk.y, a);
                        a = fmaf(q[4*i+2], kk.z, a);
                        a = fmaf(q[4*i+3], kk.w, a);
                    }
                    a += __shfl_xor_sync(0xffffffffu, a, 1);  // combine head halves
                    s = a * 0.125f;    // 1/sqrt(64)
                } else {
                    float dummy = 0.f;
                    dummy += __shfl_xor_sync(0xffffffffu, dummy, 1);
                }
                sv[dd] = s;
            }
            float m = sv[0];
#pragma unroll
            for (int dd = 1; dd < 11; dd++) m = fmaxf(m, sv[dd]);
            float sum = 0.f;
#pragma unroll
            for (int dd = 0; dd < 11; dd++) sum += __expf(sv[dd] - m);
            float inv = __fdividef(1.f, sum);
#pragma unroll
            for (int i = 0; i < 32; i++) o[i] = 0.f;
#pragma unroll
            for (int dd = 0; dd < 11; dd++) {
                int j = row + deltas[dd];
                if ((unsigned)j < 128u) {
                    float wj = __expf(sv[dd] - m) * inv;
                    const float* vp = &Vs[j * LDKV + kvs];
#pragma unroll
                    for (int i = 0; i < 8; i++) {
                        float4 vv = *(const float4*)&vp[i * 4];
                        o[4*i]   = fmaf(wj, vv.x, o[4*i]);
                        o[4*i+1] = fmaf(wj, vv.y, o[4*i+1]);
                        o[4*i+2] = fmaf(wj, vv.z, o[4*i+2]);
                        o[4*i+3] = fmaf(wj, vv.w, o[4*i+3]);
                    }
                }
            }
        }
        __syncthreads();                                     // all Q reads done
        stage_rowvals(o, smem, row, c0);                     // O -> H buffers
        __syncthreads();                                     // O staged

        gemm_mma(a_hi_lane, a_lo_lane, g_wfrag + (4*l + 3) * 4096 + wfoff, mw, dK);
        __syncthreads();                                     // all O reads done
        if (l < 3) {
            epi_bf16(dK, smem, bo + l * 128, mw, nw, lane);  // H_new staged
        } else {
            float* ob = out + (size_t)bi * 8388608 + (size_t)t * 128;
            epi_out(dK, ob, bo + l * 128, mw, nw, lane);
        }
    }
}

extern "C" void kernel_launch(void* const* d_in, const int* in_sizes, int n_in,
                              void* d_out, int out_size)
{
    const float* x  = (const float*)d_in[0];
    const float* Wq = (const float*)d_in[1];
    const float* bq = (const float*)d_in[2];
    const float* Wk = (const float*)d_in[3];
    const float* bk = (const float*)d_in[4];
    const float* Wv = (const float*)d_in[5];
    const float* bv = (const float*)d_in[6];
    const float* Wo = (const float*)d_in[7];
    const float* bo = (const float*)d_in[8];
    float* out = (float*)d_out;

    const int NB = in_sizes[0] / (128 * TT * 128);   // batch (4)

    prep_w<<<17, 256>>>(Wq, Wk, Wv, Wo);

    cudaFuncSetAttribute(hattn_mma, cudaFuncAttributeMaxDynamicSharedMemorySize, SMEM_TOTAL);
    hattn_mma<<<NB * TT, NTHREADS, SMEM_TOTAL>>>(x, bq, bk, bv, bo, out);
}

// round 11
// speedup vs baseline: 1.2597x; 1.2597x over previous
#include <cuda_runtime.h>
#include <cuda_fp16.h>
#include <cstdint>

// HarmonicAwaredAttention via warp-level HMMA (mma.sync, arch-agnostic PTX).
// R11: fp16 2-term split (D = Ah*B + Al*B, B single-rounded fp16).
//      33% less MMA work than bf16 3-term; B table + B LDG traffic halved.
//      Structure = R9 (proven): 512 threads, warp grid 4(M)x4(N), tile 32x32,
//      full-ks B prefetch. Attention scalar fp32 sparse-harmonic.

#define TT 512
#define NTHREADS 512
#define LDH_B  272            // fp16 row stride in bytes (136 elems)
#define LDKV   144            // fp32 row stride (floats) for K/V, skewed
#define LDQ    132            // fp32 row stride (floats) for Q overlay

// smem byte offsets
#define HHI_OFF 0
#define HLO_OFF 34816
#define QS_OFF  0              // fp32 Q overlays H region (sequenced by syncs)
#define KS_OFF  69632
#define VS_OFF  143360
#define SMEM_TOTAL 217088

// weights, fragment-linear uint2 (fp16): [gemm][ks 0..7][j 0..15][lane 0..31]
__device__ __align__(16) uint2 g_wfrag[16 * 4096];
__device__ float g_pe[128 * 128];     // g_pe[c*128 + f]

__device__ __forceinline__ uint32_t smem_u32(const void* p) {
    uint32_t a;
    asm("{ .reg .u64 t; cvta.to.shared.u64 t, %1; cvt.u32.u64 %0, t; }" : "=r"(a) : "l"(p));
    return a;
}

#define LDSM(r, addr) \
    asm volatile("ldmatrix.sync.aligned.m8n8.x4.shared.b16 {%0,%1,%2,%3}, [%4];" \
        : "=r"((r)[0]), "=r"((r)[1]), "=r"((r)[2]), "=r"((r)[3]) : "r"(addr))

#define MMA(dp, a, bx, by) \
    asm volatile("mma.sync.aligned.m16n8k16.row.col.f32.f16.f16.f32 " \
        "{%0,%1,%2,%3},{%4,%5,%6,%7},{%8,%9},{%0,%1,%2,%3};" \
        : "+f"((dp)[0]), "+f"((dp)[1]), "+f"((dp)[2]), "+f"((dp)[3]) \
        : "r"((a)[0]), "r"((a)[1]), "r"((a)[2]), "r"((a)[3]), "r"(bx), "r"(by))

// ---------------- prologue: fragment-pack weights + PE table ----------------
// gemm g = 4*layer + {0:Wk,1:Wv,2:Wq,3:Wo}.  B[n][k] = W[k][n], fp16 single-rounded.
// entry e: lane=e&31, j=(e>>5)&15 (n-tile), ks=e>>9.
// lane fragment: n = 8j + (lane>>2); k0 = 16ks + 2(lane&3).
__global__ void prep_w(const float* __restrict__ Wq, const float* __restrict__ Wk,
                       const float* __restrict__ Wv, const float* __restrict__ Wo)
{
    int g = blockIdx.x;
    if (g == 16) {   // PE table
        for (int idx = threadIdx.x; idx < 128 * 128; idx += blockDim.x) {
            int c = idx >> 7, f = idx & 127;
            float e     = (float)(c & ~1) * (1.0f / 128.0f);
            float denom = exp2f(e * 13.287712379549449f);   // 10000^(i/128)
            float ang   = (float)f / denom;
            g_pe[c * 128 + f] = (c & 1) ? cosf(ang) : sinf(ang);
        }
        return;
    }
    int l = g >> 2, m = g & 3;
    const float* src = (m == 0 ? Wk : m == 1 ? Wv : m == 2 ? Wq : Wo) + l * 16384;
    for (int e = threadIdx.x; e < 4096; e += blockDim.x) {
        int lane = e & 31, j = (e >> 5) & 15, ks = e >> 9;
        int n  = 8 * j + (lane >> 2);
        int k0 = 16 * ks + 2 * (lane & 3);
        float w00 = src[k0 * 128 + n],       w01 = src[(k0 + 1) * 128 + n];
        float w10 = src[(k0 + 8) * 128 + n], w11 = src[(k0 + 9) * 128 + n];
        __half2 h0 = __floats2half2_rn(w00, w01);
        __half2 h1 = __floats2half2_rn(w10, w11);
        uint2 o;
        o.x = *(uint32_t*)&h0;
        o.y = *(uint32_t*)&h1;
        g_wfrag[g * 4096 + e] = o;
    }
}

// ------------- GEMM: warp (mw,nw) computes D[32 rows x 32 cols] -------------
// d[mt*4 + jj][4]: mt in 0..1 (16-row tiles), jj in 0..3 (8-col tiles).
// wf pre-offset: g_wfrag + g*4096 + (4*nw)*32 + lane.  2 MMA terms per (mt,jj).
__device__ __forceinline__ void gemm_mma(uint32_t a_hi_lane, uint32_t a_lo_lane,
                                         const uint2* __restrict__ wf,
                                         int mw, float (*d)[4])
{
#pragma unroll
    for (int i = 0; i < 8; i++) { d[i][0] = 0.f; d[i][1] = 0.f; d[i][2] = 0.f; d[i][3] = 0.f; }

    uint2 b[4];
#pragma unroll
    for (int jj = 0; jj < 4; jj++) b[jj] = __ldg(wf + jj * 32);

    const uint32_t a_row_off = (uint32_t)(mw * 32) * LDH_B;

#pragma unroll
    for (int ks = 0; ks < 8; ks++) {
        uint32_t ah[2][4], al[2][4];
#pragma unroll
        for (int mt = 0; mt < 2; mt++) {
            uint32_t off = a_row_off + (uint32_t)(mt * 16) * LDH_B + (uint32_t)ks * 32;
            LDSM(ah[mt], a_hi_lane + off);
            LDSM(al[mt], a_lo_lane + off);
        }
        uint2 nb[4];
        {   // full-ks-ahead prefetch (wraps at end; harmless reload)
            const uint2* p = wf + (((ks + 1) & 7) * 512);
#pragma unroll
            for (int jj = 0; jj < 4; jj++) nb[jj] = __ldg(p + jj * 32);
        }
#pragma unroll
        for (int mt = 0; mt < 2; mt++) {
#pragma unroll
            for (int jj = 0; jj < 4; jj++) {
                MMA(d[mt * 4 + jj], ah[mt], b[jj].x, b[jj].y);   // Ah*B
                MMA(d[mt * 4 + jj], al[mt], b[jj].x, b[jj].y);   // Al*B
            }
        }
#pragma unroll
        for (int jj = 0; jj < 4; jj++) b[jj] = nb[jj];
    }
}

// D + bias -> fp32 smem buffer; stride ldf, column skew cs (floats).
__device__ __forceinline__ void epi_f32(float (*d)[4], float* buf, const float* bias,
                                        int mw, int nw, int lane, int ldf, int cs)
{
    int rq = lane >> 2, cq = 2 * (lane & 3);
#pragma unroll
    for (int jj = 0; jj < 4; jj++) {
        int c = 32 * nw + 8 * jj + cq;
        float b0 = __ldg(&bias[c]), b1 = __ldg(&bias[c + 1]);
#pragma unroll
        for (int mt = 0; mt < 2; mt++) {
            int r0 = 32 * mw + 16 * mt + rq;
            float2 v0 = make_float2(d[mt*4+jj][0] + b0, d[mt*4+jj][1] + b1);
            float2 v1 = make_float2(d[mt*4+jj][2] + b0, d[mt*4+jj][3] + b1);
            *(float2*)&buf[r0 * ldf + c + cs]       = v0;
            *(float2*)&buf[(r0 + 8) * ldf + c + cs] = v1;
        }
    }
}

// D + bias -> fp16 hi/lo H buffers
__device__ __forceinline__ void epi_f16(float (*d)[4], unsigned char* sm,
                                        const float* bias, int mw, int nw, int lane)
{
    int rq = lane >> 2, cq = 2 * (lane & 3);
#pragma unroll
    for (int jj = 0; jj < 4; jj++) {
        int c = 32 * nw + 8 * jj + cq;
        float b0 = __ldg(&bias[c]), b1 = __ldg(&bias[c + 1]);
#pragma unroll
        for (int mt = 0; mt < 2; mt++) {
            int r0 = 32 * mw + 16 * mt + rq;
#pragma unroll
            for (int hh = 0; hh < 2; hh++) {
                int r = r0 + 8 * hh;
                float v0 = d[mt*4+jj][2*hh]     + b0;
                float v1 = d[mt*4+jj][2*hh + 1] + b1;
                __half2 hi2 = __floats2half2_rn(v0, v1);
                float2 hf = __half22float2(hi2);
                __half2 lo2 = __floats2half2_rn(v0 - hf.x, v1 - hf.y);
                *(uint32_t*)(sm + HHI_OFF + r * LDH_B + c * 2) = *(uint32_t*)&hi2;
                *(uint32_t*)(sm + HLO_OFF + r * LDH_B + c * 2) = *(uint32_t*)&lo2;
            }
        }
    }
}

// D + bias -> gmem out (transposed: out[c][r], channel stride 65536)
__device__ __forceinline__ void epi_out(float (*d)[4], float* ob, const float* bias,
                                        int mw, int nw, int lane)
{
    int rq = lane >> 2, cq = 2 * (lane & 3);
#pragma unroll
    for (int jj = 0; jj < 4; jj++) {
        int c = 32 * nw + 8 * jj + cq;
        float b0 = __ldg(&bias[c]), b1 = __ldg(&bias[c + 1]);
#pragma unroll
        for (int mt = 0; mt < 2; mt++) {
            int r0 = 32 * mw + 16 * mt + rq;
            ob[(size_t)c * 65536 + r0]           = d[mt*4+jj][0] + b0;
            ob[(size_t)(c + 1) * 65536 + r0]     = d[mt*4+jj][1] + b1;
            ob[(size_t)c * 65536 + r0 + 8]       = d[mt*4+jj][2] + b0;
            ob[(size_t)(c + 1) * 65536 + r0 + 8] = d[mt*4+jj][3] + b1;
        }
    }
}

// 32 fp32 vals (one row, one 32-col group) -> fp16 hi/lo into H buffers
__device__ __forceinline__ void stage_rowvals(const float* v, unsigned char* sm,
                                              int row, int c0)
{
#pragma unroll
    for (int i = 0; i < 16; i++) {
        float a = v[2 * i], b = v[2 * i + 1];
        __half2 hi2 = __floats2half2_rn(a, b);
        float2 hf = __half22float2(hi2);
        __half2 lo2 = __floats2half2_rn(a - hf.x, b - hf.y);
        *(uint32_t*)(sm + HHI_OFF + row * LDH_B + (c0 + 2 * i) * 2) = *(uint32_t*)&hi2;
        *(uint32_t*)(sm + HLO_OFF + row * LDH_B + (c0 + 2 * i) * 2) = *(uint32_t*)&lo2;
    }
}

extern __shared__ unsigned char smem[];

__global__ void __launch_bounds__(NTHREADS, 1)
hattn_mma(const float* __restrict__ x,
          const float* __restrict__ bq, const float* __restrict__ bk,
          const float* __restrict__ bv, const float* __restrict__ bo,
          float* __restrict__ out)
{
    const int tid = threadIdx.x;
    const int w = tid >> 5, lane = tid & 31;
    const int mw = w & 3, nw = w >> 2;          // warp grid 4(M) x 4(N)
    const int bi = blockIdx.x / TT;
    const int t  = blockIdx.x % TT;

    float* Qs = (float*)(smem + QS_OFF);
    float* Ks = (float*)(smem + KS_OFF);
    float* Vs = (float*)(smem + VS_OFF);

    const uint32_t smbase = smem_u32(smem);
    const uint32_t a_hi_lane = smbase + HHI_OFF + (lane & 15) * LDH_B + (lane >> 4) * 16;
    const uint32_t a_lo_lane = smbase + HLO_OFF + (lane & 15) * LDH_B + (lane >> 4) * 16;

    const int wfoff = (4 * nw) * 32 + lane;     // B fragment base offset for this warp

    // attention / staging mapping: thread owns (row, 32-col group qg)
    const int row = tid >> 2;
    const int qg  = tid & 3;                    // head = qg>>1, half = qg&1
    const int c0  = 32 * qg;
    const int kvs = c0 + 4 * qg;                // skewed col offset into Ks/Vs

    // ---- stage H = x + PE ----
    {
        const float* xb = x + (size_t)bi * 8388608 + (size_t)t * 128;
        float v[32];
#pragma unroll
        for (int c = 0; c < 32; c++)
            v[c] = xb[(size_t)(c0 + c) * 65536 + row] + g_pe[(c0 + c) * 128 + row];
        stage_rowvals(v, smem, row, c0);
    }

    const int deltas[11] = {-124, -111, -96, -76, -48, 0, 48, 76, 96, 111, 124};
    float d[8][4];

#pragma unroll 1
    for (int l = 0; l < 4; l++) {
        __syncthreads();                                     // H staged/visible

        gemm_mma(a_hi_lane, a_lo_lane, g_wfrag + (4*l + 0) * 4096 + wfoff, mw, d);
        epi_f32(d, Ks, bk + l * 128, mw, nw, lane, LDKV, 4 * nw);
        gemm_mma(a_hi_lane, a_lo_lane, g_wfrag + (4*l + 1) * 4096 + wfoff, mw, d);
        epi_f32(d, Vs, bv + l * 128, mw, nw, lane, LDKV, 4 * nw);
        gemm_mma(a_hi_lane, a_lo_lane, g_wfrag + (4*l + 2) * 4096 + wfoff, mw, d);
        __syncthreads();                                     // all H reads done
        epi_f32(d, Qs, bq + l * 128, mw, nw, lane, LDQ, 0);  // Q overlays H region
        __syncthreads();                                     // Q/K/V visible

        // ---- sparse harmonic attention: thread owns (row, qg) ----
        float o[32];
        {
            float q[32];
            const float* qp = &Qs[row * LDQ + c0];
#pragma unroll
            for (int i = 0; i < 32; i++) q[i] = qp[i];

            float sv[11];
#pragma unroll
            for (int dd = 0; dd < 11; dd++) {
                int j = row + deltas[dd];
                float s = -1e30f;
                if ((unsigned)j < 128u) {
                    const float* kp = &Ks[j * LDKV + kvs];
                    float a = 0.f;
#pragma unroll
                    for (int i = 0; i < 8; i++) {
                        float4 kk = *(const float4*)&kp[i * 4];
                        a = fmaf(q[4*i],   kk.x, a);
                        a = fmaf(q[4*i+1], kk.y, a);
                        a = fmaf(q[4*i+2], kk.z, a);
                        a = fmaf(q[4*i+3], kk.w, a);
                    }
                    a += __shfl_xor_sync(0xffffffffu, a, 1);  // combine head halves
                    s = a * 0.125f;    // 1/sqrt(64)
                } else {
                    float dummy = 0.f;
                    dummy += __shfl_xor_sync(0xffffffffu, dummy, 1);
                }
                sv[dd] = s;
            }
            float m = sv[0];
#pragma unroll
            for (int dd = 1; dd < 11; dd++) m = fmaxf(m, sv[dd]);
            float sum = 0.f;
#pragma unroll
            for (int dd = 0; dd < 11; dd++) sum += __expf(sv[dd] - m);
            float inv = __fdividef(1.f, sum);
#pragma unroll
            for (int i = 0; i < 32; i++) o[i] = 0.f;
#pragma unroll
            for (int dd = 0; dd < 11; dd++) {
                int j = row + deltas[dd];
                if ((unsigned)j < 128u) {
                    float wj = __expf(sv[dd] - m) * inv;
                    const float* vp = &Vs[j * LDKV + kvs];
#pragma unroll
                    for (int i = 0; i < 8; i++) {
                        float4 vv = *(const float4*)&vp[i * 4];
                        o[4*i]   = fmaf(wj, vv.x, o[4*i]);
                        o[4*i+1] = fmaf(wj, vv.y, o[4*i+1]);
                        o[4*i+2] = fmaf(wj, vv.z, o[4*i+2]);
                        o[4*i+3] = fmaf(wj, vv.w, o[4*i+3]);
                    }
                }
            }
        }
        __syncthreads();                                     // all Q reads done
        stage_rowvals(o, smem, row, c0);                     // O -> H buffers
        __syncthreads();                                     // O staged

        gemm_mma(a_hi_lane, a_lo_lane, g_wfrag + (4*l + 3) * 4096 + wfoff, mw, d);
        __syncthreads();                                     // all O reads done
        if (l < 3) {
            epi_f16(d, smem, bo + l * 128, mw, nw, lane);    // H_new staged
        } else {
            float* ob = out + (size_t)bi * 8388608 + (size_t)t * 128;
            epi_out(d, ob, bo + l * 128, mw, nw, lane);
        }
    }
}

extern "C" void kernel_launch(void* const* d_in, const int* in_sizes, int n_in,
                              void* d_out, int out_size)
{
    const float* x  = (const float*)d_in[0];
    const float* Wq = (const float*)d_in[1];
    const float* bq = (const float*)d_in[2];
    const float* Wk = (const float*)d_in[3];
    const float* bk = (const float*)d_in[4];
    const float* Wv = (const float*)d_in[5];
    const float* bv = (const float*)d_in[6];
    const float* Wo = (const float*)d_in[7];
    const float* bo = (const float*)d_in[8];
    float* out = (float*)d_out;

    const int NB = in_sizes[0] / (128 * TT * 128);   // batch (4)

    prep_w<<<17, 256>>>(Wq, Wk, Wv, Wo);

    cudaFuncSetAttribute(hattn_mma, cudaFuncAttributeMaxDynamicSharedMemorySize, SMEM_TOTAL);
    hattn_mma<<<NB * TT, NTHREADS, SMEM_TOTAL>>>(x, bq, bk, bv, bo, out);
}

// round 12
// speedup vs baseline: 1.3242x; 1.0512x over previous
#include <cuda_runtime.h>
#include <cuda_fp16.h>
#include <cstdint>

// HarmonicAwaredAttention via warp-level HMMA (mma.sync, arch-agnostic PTX).
// R12: V stored fp16 in smem (chunk-interleaved conflict-free layout) -> V-pass
//      LDS traffic halved. K stays fp32 (softmax error amplification).
//      Convergent shuffle restructure. Else identical to R11 (975us).
// GEMMs: m16n8k16 fp16 MMA, 2-term split (Ah*B + Al*B), B single-rounded fp16.

#define TT 512
#define NTHREADS 512
#define LDH_B  272            // fp16 row stride in bytes (136 elems)
#define LDKV   144            // fp32 row stride (floats) for K, skewed
#define LDQ    132            // fp32 row stride (floats) for Q overlay
#define LDV_B  272            // V fp16 row stride in bytes

// smem byte offsets
#define HHI_OFF 0
#define HLO_OFF 34816
#define QS_OFF  0              // fp32 Q overlays H region (sequenced by syncs)
#define KS_OFF  69632
#define VS_OFF  143360         // fp16 V, 128*272 = 34816 bytes
#define SMEM_TOTAL 178176

// weights, fragment-linear uint2 (fp16): [gemm][ks 0..7][j 0..15][lane 0..31]
__device__ __align__(16) uint2 g_wfrag[16 * 4096];
__device__ float g_pe[128 * 128];     // g_pe[c*128 + f]

__device__ __forceinline__ uint32_t smem_u32(const void* p) {
    uint32_t a;
    asm("{ .reg .u64 t; cvta.to.shared.u64 t, %1; cvt.u32.u64 %0, t; }" : "=r"(a) : "l"(p));
    return a;
}

#define LDSM(r, addr) \
    asm volatile("ldmatrix.sync.aligned.m8n8.x4.shared.b16 {%0,%1,%2,%3}, [%4];" \
        : "=r"((r)[0]), "=r"((r)[1]), "=r"((r)[2]), "=r"((r)[3]) : "r"(addr))

#define MMA(dp, a, bx, by) \
    asm volatile("mma.sync.aligned.m16n8k16.row.col.f32.f16.f16.f32 " \
        "{%0,%1,%2,%3},{%4,%5,%6,%7},{%8,%9},{%0,%1,%2,%3};" \
        : "+f"((dp)[0]), "+f"((dp)[1]), "+f"((dp)[2]), "+f"((dp)[3]) \
        : "r"((a)[0]), "r"((a)[1]), "r"((a)[2]), "r"((a)[3]), "r"(bx), "r"(by))

// V fp16 layout: byte offset(r, C) = r*272 + (C>>5)*32 + ((i&1)<<7) + ((i>>1)<<4) + (C&7)*2
// where i = (C&31)>>3. Per quarter-warp (2 rows x 4 qg) the 16B chunks hit
// 8 distinct 128B-phase slots -> conflict-free LDS.128 reads.

// ---------------- prologue: fragment-pack weights + PE table ----------------
__global__ void prep_w(const float* __restrict__ Wq, const float* __restrict__ Wk,
                       const float* __restrict__ Wv, const float* __restrict__ Wo)
{
    int g = blockIdx.x;
    if (g == 16) {   // PE table
        for (int idx = threadIdx.x; idx < 128 * 128; idx += blockDim.x) {
            int c = idx >> 7, f = idx & 127;
            float e     = (float)(c & ~1) * (1.0f / 128.0f);
            float denom = exp2f(e * 13.287712379549449f);   // 10000^(i/128)
            float ang   = (float)f / denom;
            g_pe[c * 128 + f] = (c & 1) ? cosf(ang) : sinf(ang);
        }
        return;
    }
    int l = g >> 2, m = g & 3;
    const float* src = (m == 0 ? Wk : m == 1 ? Wv : m == 2 ? Wq : Wo) + l * 16384;
    for (int e = threadIdx.x; e < 4096; e += blockDim.x) {
        int lane = e & 31, j = (e >> 5) & 15, ks = e >> 9;
        int n  = 8 * j + (lane >> 2);
        int k0 = 16 * ks + 2 * (lane & 3);
        float w00 = src[k0 * 128 + n],       w01 = src[(k0 + 1) * 128 + n];
        float w10 = src[(k0 + 8) * 128 + n], w11 = src[(k0 + 9) * 128 + n];
        __half2 h0 = __floats2half2_rn(w00, w01);
        __half2 h1 = __floats2half2_rn(w10, w11);
        uint2 o;
        o.x = *(uint32_t*)&h0;
        o.y = *(uint32_t*)&h1;
        g_wfrag[g * 4096 + e] = o;
    }
}

// ------------- GEMM: warp (mw,nw) computes D[32 rows x 32 cols] -------------
__device__ __forceinline__ void gemm_mma(uint32_t a_hi_lane, uint32_t a_lo_lane,
                                         const uint2* __restrict__ wf,
                                         int mw, float (*d)[4])
{
#pragma unroll
    for (int i = 0; i < 8; i++) { d[i][0] = 0.f; d[i][1] = 0.f; d[i][2] = 0.f; d[i][3] = 0.f; }

    uint2 b[4];
#pragma unroll
    for (int jj = 0; jj < 4; jj++) b[jj] = __ldg(wf + jj * 32);

    const uint32_t a_row_off = (uint32_t)(mw * 32) * LDH_B;

#pragma unroll
    for (int ks = 0; ks < 8; ks++) {
        uint32_t ah[2][4], al[2][4];
#pragma unroll
        for (int mt = 0; mt < 2; mt++) {
            uint32_t off = a_row_off + (uint32_t)(mt * 16) * LDH_B + (uint32_t)ks * 32;
            LDSM(ah[mt], a_hi_lane + off);
            LDSM(al[mt], a_lo_lane + off);
        }
        uint2 nb[4];
        {   // full-ks-ahead prefetch (wraps at end; harmless reload)
            const uint2* p = wf + (((ks + 1) & 7) * 512);
#pragma unroll
            for (int jj = 0; jj < 4; jj++) nb[jj] = __ldg(p + jj * 32);
        }
#pragma unroll
        for (int mt = 0; mt < 2; mt++) {
#pragma unroll
            for (int jj = 0; jj < 4; jj++) {
                MMA(d[mt * 4 + jj], ah[mt], b[jj].x, b[jj].y);   // Ah*B
                MMA(d[mt * 4 + jj], al[mt], b[jj].x, b[jj].y);   // Al*B
            }
        }
#pragma unroll
        for (int jj = 0; jj < 4; jj++) b[jj] = nb[jj];
    }
}

// D + bias -> fp32 smem buffer; stride ldf, column skew cs (floats).
__device__ __forceinline__ void epi_f32(float (*d)[4], float* buf, const float* bias,
                                        int mw, int nw, int lane, int ldf, int cs)
{
    int rq = lane >> 2, cq = 2 * (lane & 3);
#pragma unroll
    for (int jj = 0; jj < 4; jj++) {
        int c = 32 * nw + 8 * jj + cq;
        float b0 = __ldg(&bias[c]), b1 = __ldg(&bias[c + 1]);
#pragma unroll
        for (int mt = 0; mt < 2; mt++) {
            int r0 = 32 * mw + 16 * mt + rq;
            float2 v0 = make_float2(d[mt*4+jj][0] + b0, d[mt*4+jj][1] + b1);
            float2 v1 = make_float2(d[mt*4+jj][2] + b0, d[mt*4+jj][3] + b1);
            *(float2*)&buf[r0 * ldf + c + cs]       = v0;
            *(float2*)&buf[(r0 + 8) * ldf + c + cs] = v1;
        }
    }
}

// D + bias -> V fp16 smem (chunk-interleaved layout). STS.32, conflict-free.
__device__ __forceinline__ void epi_v16(float (*d)[4], unsigned char* vb,
                                        const float* bias, int mw, int nw, int lane)
{
    int rq = lane >> 2, cq = 2 * (lane & 3);
#pragma unroll
    for (int jj = 0; jj < 4; jj++) {
        int c = 32 * nw + 8 * jj + cq;
        float b0 = __ldg(&bias[c]), b1 = __ldg(&bias[c + 1]);
        // col part: qg = nw, chunk i = jj, within-chunk pos = cq
        int colpart = nw * 32 + ((jj & 1) << 7) + ((jj >> 1) << 4) + cq * 2;
#pragma unroll
        for (int mt = 0; mt < 2; mt++) {
            int r0 = 32 * mw + 16 * mt + rq;
            __half2 h0 = __floats2half2_rn(d[mt*4+jj][0] + b0, d[mt*4+jj][1] + b1);
            __half2 h1 = __floats2half2_rn(d[mt*4+jj][2] + b0, d[mt*4+jj][3] + b1);
            *(uint32_t*)(vb + r0 * LDV_B + colpart)       = *(uint32_t*)&h0;
            *(uint32_t*)(vb + (r0 + 8) * LDV_B + colpart) = *(uint32_t*)&h1;
        }
    }
}

// D + bias -> fp16 hi/lo H buffers
__device__ __forceinline__ void epi_f16(float (*d)[4], unsigned char* sm,
                                        const float* bias, int mw, int nw, int lane)
{
    int rq = lane >> 2, cq = 2 * (lane & 3);
#pragma unroll
    for (int jj = 0; jj < 4; jj++) {
        int c = 32 * nw + 8 * jj + cq;
        float b0 = __ldg(&bias[c]), b1 = __ldg(&bias[c + 1]);
#pragma unroll
        for (int mt = 0; mt < 2; mt++) {
            int r0 = 32 * mw + 16 * mt + rq;
#pragma unroll
            for (int hh = 0; hh < 2; hh++) {
                int r = r0 + 8 * hh;
                float v0 = d[mt*4+jj][2*hh]     + b0;
                float v1 = d[mt*4+jj][2*hh + 1] + b1;
                __half2 hi2 = __floats2half2_rn(v0, v1);
                float2 hf = __half22float2(hi2);
                __half2 lo2 = __floats2half2_rn(v0 - hf.x, v1 - hf.y);
                *(uint32_t*)(sm + HHI_OFF + r * LDH_B + c * 2) = *(uint32_t*)&hi2;
                *(uint32_t*)(sm + HLO_OFF + r * LDH_B + c * 2) = *(uint32_t*)&lo2;
            }
        }
    }
}

// D + bias -> gmem out (transposed: out[c][r], channel stride 65536)
__device__ __forceinline__ void epi_out(float (*d)[4], float* ob, const float* bias,
                                        int mw, int nw, int lane)
{
    int rq = lane >> 2, cq = 2 * (lane & 3);
#pragma unroll
    for (int jj = 0; jj < 4; jj++) {
        int c = 32 * nw + 8 * jj + cq;
        float b0 = __ldg(&bias[c]), b1 = __ldg(&bias[c + 1]);
#pragma unroll
        for (int mt = 0; mt < 2; mt++) {
            int r0 = 32 * mw + 16 * mt + rq;
            ob[(size_t)c * 65536 + r0]           = d[mt*4+jj][0] + b0;
            ob[(size_t)(c + 1) * 65536 + r0]     = d[mt*4+jj][1] + b1;
            ob[(size_t)c * 65536 + r0 + 8]       = d[mt*4+jj][2] + b0;
            ob[(size_t)(c + 1) * 65536 + r0 + 8] = d[mt*4+jj][3] + b1;
        }
    }
}

// 32 fp32 vals (one row, one 32-col group) -> fp16 hi/lo into H buffers
__device__ __forceinline__ void stage_rowvals(const float* v, unsigned char* sm,
                                              int row, int c0)
{
#pragma unroll
    for (int i = 0; i < 16; i++) {
        float a = v[2 * i], b = v[2 * i + 1];
        __half2 hi2 = __floats2half2_rn(a, b);
        float2 hf = __half22float2(hi2);
        __half2 lo2 = __floats2half2_rn(a - hf.x, b - hf.y);
        *(uint32_t*)(sm + HHI_OFF + row * LDH_B + (c0 + 2 * i) * 2) = *(uint32_t*)&hi2;
        *(uint32_t*)(sm + HLO_OFF + row * LDH_B + (c0 + 2 * i) * 2) = *(uint32_t*)&lo2;
    }
}

extern __shared__ unsigned char smem[];

__global__ void __launch_bounds__(NTHREADS, 1)
hattn_mma(const float* __restrict__ x,
          const float* __restrict__ bq, const float* __restrict__ bk,
          const float* __restrict__ bv, const float* __restrict__ bo,
          float* __restrict__ out)
{
    const int tid = threadIdx.x;
    const int w = tid >> 5, lane = tid & 31;
    const int mw = w & 3, nw = w >> 2;          // warp grid 4(M) x 4(N)
    const int bi = blockIdx.x / TT;
    const int t  = blockIdx.x % TT;

    float* Qs = (float*)(smem + QS_OFF);
    float* Ks = (float*)(smem + KS_OFF);
    unsigned char* Vh = smem + VS_OFF;

    const uint32_t smbase = smem_u32(smem);
    const uint32_t a_hi_lane = smbase + HHI_OFF + (lane & 15) * LDH_B + (lane >> 4) * 16;
    const uint32_t a_lo_lane = smbase + HLO_OFF + (lane & 15) * LDH_B + (lane >> 4) * 16;

    const int wfoff = (4 * nw) * 32 + lane;     // B fragment base offset for this warp

    // attention / staging mapping: thread owns (row, 32-col group qg)
    const int row = tid >> 2;
    const int qg  = tid & 3;                    // head = qg>>1, half = qg&1
    const int c0  = 32 * qg;
    const int kvs = c0 + 4 * qg;                // skewed col offset into Ks

    // ---- stage H = x + PE ----
    {
        const float* xb = x + (size_t)bi * 8388608 + (size_t)t * 128;
        float v[32];
#pragma unroll
        for (int c = 0; c < 32; c++)
            v[c] = xb[(size_t)(c0 + c) * 65536 + row] + g_pe[(c0 + c) * 128 + row];
        stage_rowvals(v, smem, row, c0);
    }

    const int deltas[11] = {-124, -111, -96, -76, -48, 0, 48, 76, 96, 111, 124};
    float d[8][4];

#pragma unroll 1
    for (int l = 0; l < 4; l++) {
        __syncthreads();                                     // H staged/visible

        gemm_mma(a_hi_lane, a_lo_lane, g_wfrag + (4*l + 0) * 4096 + wfoff, mw, d);
        epi_f32(d, Ks, bk + l * 128, mw, nw, lane, LDKV, 4 * nw);
        gemm_mma(a_hi_lane, a_lo_lane, g_wfrag + (4*l + 1) * 4096 + wfoff, mw, d);
        epi_v16(d, Vh, bv + l * 128, mw, nw, lane);
        gemm_mma(a_hi_lane, a_lo_lane, g_wfrag + (4*l + 2) * 4096 + wfoff, mw, d);
        __syncthreads();                                     // all H reads done
        epi_f32(d, Qs, bq + l * 128, mw, nw, lane, LDQ, 0);  // Q overlays H region
        __syncthreads();                                     // Q/K/V visible

        // ---- sparse harmonic attention: thread owns (row, qg) ----
        float o[32];
        {
            float q[32];
            const float* qp = &Qs[row * LDQ + c0];
#pragma unroll
            for (int i = 0; i < 32; i++) q[i] = qp[i];

            float sv[11];
#pragma unroll
            for (int dd = 0; dd < 11; dd++) {
                int j = row + deltas[dd];
                bool valid = (unsigned)j < 128u;
                float a = 0.f;
                if (valid) {
                    const float* kp = &Ks[j * LDKV + kvs];
#pragma unroll
                    for (int i = 0; i < 8; i++) {
                        float4 kk = *(const float4*)&kp[i * 4];
                        a = fmaf(q[4*i],   kk.x, a);
                        a = fmaf(q[4*i+1], kk.y, a);
                        a = fmaf(q[4*i+2], kk.z, a);
                        a = fmaf(q[4*i+3], kk.w, a);
                    }
                }
                a += __shfl_xor_sync(0xffffffffu, a, 1);     // combine head halves
                sv[dd] = valid ? a * 0.125f : -1e30f;        // 1/sqrt(64)
            }
            float m = sv[0];
#pragma unroll
            for (int dd = 1; dd < 11; dd++) m = fmaxf(m, sv[dd]);
            float sum = 0.f;
#pragma unroll
            for (int dd = 0; dd < 11; dd++) sum += __expf(sv[dd] - m);
            float inv = __fdividef(1.f, sum);
#pragma unroll
            for (int i = 0; i < 32; i++) o[i] = 0.f;
#pragma unroll
            for (int dd = 0; dd < 11; dd++) {
                int j = row + deltas[dd];
                if ((unsigned)j < 128u) {
                    float wj = __expf(sv[dd] - m) * inv;
                    const unsigned char* vb = Vh + j * LDV_B + qg * 32;
#pragma unroll
                    for (int i = 0; i < 4; i++) {
                        uint4 raw = *(const uint4*)(vb + ((i & 1) << 7) + ((i >> 1) << 4));
                        const __half2* hp = (const __half2*)&raw;
#pragma unroll
                        for (int tphalf = 0; tphalf < 4; tphalf++) {
                            float2 f = __half22float2(hp[tphalf]);
                            o[8*i + 2*tphalf]     = fmaf(wj, f.x, o[8*i + 2*tphalf]);
                            o[8*i + 2*tphalf + 1] = fmaf(wj, f.y, o[8*i + 2*tphalf + 1]);
                        }
                    }
                }
            }
        }
        __syncthreads();                                     // all Q reads done
        stage_rowvals(o, smem, row, c0);                     // O -> H buffers
        __syncthreads();                                     // O staged

        gemm_mma(a_hi_lane, a_lo_lane, g_wfrag + (4*l + 3) * 4096 + wfoff, mw, d);
        __syncthreads();                                     // all O reads done
        if (l < 3) {
            epi_f16(d, smem, bo + l * 128, mw, nw, lane);    // H_new staged
        } else {
            float* ob = out + (size_t)bi * 8388608 + (size_t)t * 128;
            epi_out(d, ob, bo + l * 128, mw, nw, lane);
        }
    }
}

extern "C" void kernel_launch(void* const* d_in, const int* in_sizes, int n_in,
                              void* d_out, int out_size)
{
    const float* x  = (const float*)d_in[0];
    const float* Wq = (const float*)d_in[1];
    const float* bq = (const float*)d_in[2];
    const float* Wk = (const float*)d_in[3];
    const float* bk = (const float*)d_in[4];
    const float* Wv = (const float*)d_in[5];
    const float* bv = (const float*)d_in[6];
    const float* Wo = (const float*)d_in[7];
    const float* bo = (const float*)d_in[8];
    float* out = (float*)d_out;

    const int NB = in_sizes[0] / (128 * TT * 128);   // batch (4)

    prep_w<<<17, 256>>>(Wq, Wk, Wv, Wo);

    cudaFuncSetAttribute(hattn_mma, cudaFuncAttributeMaxDynamicSharedMemorySize, SMEM_TOTAL);
    hattn_mma<<<NB * TT, NTHREADS, SMEM_TOTAL>>>(x, bq, bk, bv, bo, out);
}

// round 13
// speedup vs baseline: 1.3602x; 1.0272x over previous
#include <cuda_runtime.h>
#include <cuda_fp16.h>
#include <cstdint>

// HarmonicAwaredAttention via warp-level HMMA (mma.sync, arch-agnostic PTX).
// R13: K also fp16 in smem (same chunk-interleaved layout as V, validated R12);
//      gemm_mma stage-pipelined at (ks,mt) granularity (LDSM s+1 before MMAs of s).
// GEMMs: m16n8k16 fp16 MMA, 2-term split (Ah*B + Al*B), B single-rounded fp16.

#define TT 512
#define NTHREADS 512
#define LDH_B  272            // fp16 row stride in bytes (136 elems)
#define LDQ    132            // fp32 row stride (floats) for Q overlay
#define LDKV_B 272            // K/V fp16 row stride in bytes

// smem byte offsets
#define HHI_OFF 0
#define HLO_OFF 34816
#define QS_OFF  0              // fp32 Q overlays H region (sequenced by syncs)
#define KS_OFF  69632          // fp16 K, 34816 bytes
#define VS_OFF  104448         // fp16 V, 34816 bytes
#define SMEM_TOTAL 139264

// weights, fragment-linear uint2 (fp16): [gemm][ks 0..7][j 0..15][lane 0..31]
__device__ __align__(16) uint2 g_wfrag[16 * 4096];
__device__ float g_pe[128 * 128];     // g_pe[c*128 + f]

__device__ __forceinline__ uint32_t smem_u32(const void* p) {
    uint32_t a;
    asm("{ .reg .u64 t; cvta.to.shared.u64 t, %1; cvt.u32.u64 %0, t; }" : "=r"(a) : "l"(p));
    return a;
}

#define LDSM(r, addr) \
    asm volatile("ldmatrix.sync.aligned.m8n8.x4.shared.b16 {%0,%1,%2,%3}, [%4];" \
        : "=r"((r)[0]), "=r"((r)[1]), "=r"((r)[2]), "=r"((r)[3]) : "r"(addr))

#define MMA(dp, a, bx, by) \
    asm volatile("mma.sync.aligned.m16n8k16.row.col.f32.f16.f16.f32 " \
        "{%0,%1,%2,%3},{%4,%5,%6,%7},{%8,%9},{%0,%1,%2,%3};" \
        : "+f"((dp)[0]), "+f"((dp)[1]), "+f"((dp)[2]), "+f"((dp)[3]) \
        : "r"((a)[0]), "r"((a)[1]), "r"((a)[2]), "r"((a)[3]), "r"(bx), "r"(by))

// K/V fp16 layout: byte offset(r, C) = r*272 + (C>>5)*32 + ((i&1)<<7) + ((i>>1)<<4)
// + (C&7)*2, where i=(C&31)>>3. Conflict-free for both the epilogue STS.32 and
// the per-thread 4x LDS.128 attention reads (validated for V in R12).

// ---------------- prologue: fragment-pack weights + PE table ----------------
__global__ void prep_w(const float* __restrict__ Wq, const float* __restrict__ Wk,
                       const float* __restrict__ Wv, const float* __restrict__ Wo)
{
    int g = blockIdx.x;
    if (g == 16) {   // PE table
        for (int idx = threadIdx.x; idx < 128 * 128; idx += blockDim.x) {
            int c = idx >> 7, f = idx & 127;
            float e     = (float)(c & ~1) * (1.0f / 128.0f);
            float denom = exp2f(e * 13.287712379549449f);   // 10000^(i/128)
            float ang   = (float)f / denom;
            g_pe[c * 128 + f] = (c & 1) ? cosf(ang) : sinf(ang);
        }
        return;
    }
    int l = g >> 2, m = g & 3;
    const float* src = (m == 0 ? Wk : m == 1 ? Wv : m == 2 ? Wq : Wo) + l * 16384;
    for (int e = threadIdx.x; e < 4096; e += blockDim.x) {
        int lane = e & 31, j = (e >> 5) & 15, ks = e >> 9;
        int n  = 8 * j + (lane >> 2);
        int k0 = 16 * ks + 2 * (lane & 3);
        float w00 = src[k0 * 128 + n],       w01 = src[(k0 + 1) * 128 + n];
        float w10 = src[(k0 + 8) * 128 + n], w11 = src[(k0 + 9) * 128 + n];
        __half2 h0 = __floats2half2_rn(w00, w01);
        __half2 h1 = __floats2half2_rn(w10, w11);
        uint2 o;
        o.x = *(uint32_t*)&h0;
        o.y = *(uint32_t*)&h1;
        g_wfrag[g * 4096 + e] = o;
    }
}

// ------------- GEMM: warp (mw,nw) computes D[32 rows x 32 cols] -------------
// Stage-pipelined: LDSM of stage (ks,mt+1)/(ks+1,0) issued before MMAs of (ks,mt).
__device__ __forceinline__ void gemm_mma(uint32_t a_hi_lane, uint32_t a_lo_lane,
                                         const uint2* __restrict__ wf,
                                         int mw, float (*d)[4])
{
#pragma unroll
    for (int i = 0; i < 8; i++) { d[i][0] = 0.f; d[i][1] = 0.f; d[i][2] = 0.f; d[i][3] = 0.f; }

    const uint32_t a_row = (uint32_t)(mw * 32) * LDH_B;

    uint32_t ah[2][4], al[2][4];           // [mt-buffer][frag]
    LDSM(ah[0], a_hi_lane + a_row);        // stage (ks=0, mt=0)
    LDSM(al[0], a_lo_lane + a_row);

    uint2 b[4];
#pragma unroll
    for (int jj = 0; jj < 4; jj++) b[jj] = __ldg(wf + jj * 32);

#pragma unroll
    for (int ks = 0; ks < 8; ks++) {
        // prefetch stage (ks, mt=1)
        {
            uint32_t off = a_row + (uint32_t)(16 * LDH_B) + (uint32_t)ks * 32;
            LDSM(ah[1], a_hi_lane + off);
            LDSM(al[1], a_lo_lane + off);
        }
        // prefetch B for ks+1 (wraps; harmless reload on last)
        uint2 nb[4];
        {
            const uint2* p = wf + (((ks + 1) & 7) * 512);
#pragma unroll
            for (int jj = 0; jj < 4; jj++) nb[jj] = __ldg(p + jj * 32);
        }
        // MMAs for (ks, mt=0)
#pragma unroll
        for (int jj = 0; jj < 4; jj++) {
            MMA(d[jj], ah[0], b[jj].x, b[jj].y);
            MMA(d[jj], al[0], b[jj].x, b[jj].y);
        }
        // prefetch stage (ks+1, mt=0)
        if (ks < 7) {
            uint32_t off = a_row + (uint32_t)(ks + 1) * 32;
            LDSM(ah[0], a_hi_lane + off);
            LDSM(al[0], a_lo_lane + off);
        }
        // MMAs for (ks, mt=1)
#pragma unroll
        for (int jj = 0; jj < 4; jj++) {
            MMA(d[4 + jj], ah[1], b[jj].x, b[jj].y);
            MMA(d[4 + jj], al[1], b[jj].x, b[jj].y);
        }
#pragma unroll
        for (int jj = 0; jj < 4; jj++) b[jj] = nb[jj];
    }
}

// D + bias -> fp32 smem buffer (Q); stride ldf floats.
__device__ __forceinline__ void epi_f32(float (*d)[4], float* buf, const float* bias,
                                        int mw, int nw, int lane, int ldf)
{
    int rq = lane >> 2, cq = 2 * (lane & 3);
#pragma unroll
    for (int jj = 0; jj < 4; jj++) {
        int c = 32 * nw + 8 * jj + cq;
        float b0 = __ldg(&bias[c]), b1 = __ldg(&bias[c + 1]);
#pragma unroll
        for (int mt = 0; mt < 2; mt++) {
            int r0 = 32 * mw + 16 * mt + rq;
            float2 v0 = make_float2(d[mt*4+jj][0] + b0, d[mt*4+jj][1] + b1);
            float2 v1 = make_float2(d[mt*4+jj][2] + b0, d[mt*4+jj][3] + b1);
            *(float2*)&buf[r0 * ldf + c]       = v0;
            *(float2*)&buf[(r0 + 8) * ldf + c] = v1;
        }
    }
}

// D + bias -> fp16 smem (chunk-interleaved K/V layout). STS.32, conflict-free.
__device__ __forceinline__ void epi_h16(float (*d)[4], unsigned char* vb,
                                        const float* bias, int mw, int nw, int lane)
{
    int rq = lane >> 2, cq = 2 * (lane & 3);
#pragma unroll
    for (int jj = 0; jj < 4; jj++) {
        int c = 32 * nw + 8 * jj + cq;
        float b0 = __ldg(&bias[c]), b1 = __ldg(&bias[c + 1]);
        int colpart = nw * 32 + ((jj & 1) << 7) + ((jj >> 1) << 4) + cq * 2;
#pragma unroll
        for (int mt = 0; mt < 2; mt++) {
            int r0 = 32 * mw + 16 * mt + rq;
            __half2 h0 = __floats2half2_rn(d[mt*4+jj][0] + b0, d[mt*4+jj][1] + b1);
            __half2 h1 = __floats2half2_rn(d[mt*4+jj][2] + b0, d[mt*4+jj][3] + b1);
            *(uint32_t*)(vb + r0 * LDKV_B + colpart)       = *(uint32_t*)&h0;
            *(uint32_t*)(vb + (r0 + 8) * LDKV_B + colpart) = *(uint32_t*)&h1;
        }
    }
}

// D + bias -> fp16 hi/lo H buffers
__device__ __forceinline__ void epi_f16(float (*d)[4], unsigned char* sm,
                                        const float* bias, int mw, int nw, int lane)
{
    int rq = lane >> 2, cq = 2 * (lane & 3);
#pragma unroll
    for (int jj = 0; jj < 4; jj++) {
        int c = 32 * nw + 8 * jj + cq;
        float b0 = __ldg(&bias[c]), b1 = __ldg(&bias[c + 1]);
#pragma unroll
        for (int mt = 0; mt < 2; mt++) {
            int r0 = 32 * mw + 16 * mt + rq;
#pragma unroll
            for (int hh = 0; hh < 2; hh++) {
                int r = r0 + 8 * hh;
                float v0 = d[mt*4+jj][2*hh]     + b0;
                float v1 = d[mt*4+jj][2*hh + 1] + b1;
                __half2 hi2 = __floats2half2_rn(v0, v1);
                float2 hf = __half22float2(hi2);
                __half2 lo2 = __floats2half2_rn(v0 - hf.x, v1 - hf.y);
                *(uint32_t*)(sm + HHI_OFF + r * LDH_B + c * 2) = *(uint32_t*)&hi2;
                *(uint32_t*)(sm + HLO_OFF + r * LDH_B + c * 2) = *(uint32_t*)&lo2;
            }
        }
    }
}

// D + bias -> gmem out (transposed: out[c][r], channel stride 65536)
__device__ __forceinline__ void epi_out(float (*d)[4], float* ob, const float* bias,
                                        int mw, int nw, int lane)
{
    int rq = lane >> 2, cq = 2 * (lane & 3);
#pragma unroll
    for (int jj = 0; jj < 4; jj++) {
        int c = 32 * nw + 8 * jj + cq;
        float b0 = __ldg(&bias[c]), b1 = __ldg(&bias[c + 1]);
#pragma unroll
        for (int mt = 0; mt < 2; mt++) {
            int r0 = 32 * mw + 16 * mt + rq;
            ob[(size_t)c * 65536 + r0]           = d[mt*4+jj][0] + b0;
            ob[(size_t)(c + 1) * 65536 + r0]     = d[mt*4+jj][1] + b1;
            ob[(size_t)c * 65536 + r0 + 8]       = d[mt*4+jj][2] + b0;
            ob[(size_t)(c + 1) * 65536 + r0 + 8] = d[mt*4+jj][3] + b1;
        }
    }
}

// 32 fp32 vals (one row, one 32-col group) -> fp16 hi/lo into H buffers
__device__ __forceinline__ void stage_rowvals(const float* v, unsigned char* sm,
                                              int row, int c0)
{
#pragma unroll
    for (int i = 0; i < 16; i++) {
        float a = v[2 * i], b = v[2 * i + 1];
        __half2 hi2 = __floats2half2_rn(a, b);
        float2 hf = __half22float2(hi2);
        __half2 lo2 = __floats2half2_rn(a - hf.x, b - hf.y);
        *(uint32_t*)(sm + HHI_OFF + row * LDH_B + (c0 + 2 * i) * 2) = *(uint32_t*)&hi2;
        *(uint32_t*)(sm + HLO_OFF + row * LDH_B + (c0 + 2 * i) * 2) = *(uint32_t*)&lo2;
    }
}

extern __shared__ unsigned char smem[];

__global__ void __launch_bounds__(NTHREADS, 1)
hattn_mma(const float* __restrict__ x,
          const float* __restrict__ bq, const float* __restrict__ bk,
          const float* __restrict__ bv, const float* __restrict__ bo,
          float* __restrict__ out)
{
    const int tid = threadIdx.x;
    const int w = tid >> 5, lane = tid & 31;
    const int mw = w & 3, nw = w >> 2;          // warp grid 4(M) x 4(N)
    const int bi = blockIdx.x / TT;
    const int t  = blockIdx.x % TT;

    float* Qs = (float*)(smem + QS_OFF);
    unsigned char* Kh = smem + KS_OFF;
    unsigned char* Vh = smem + VS_OFF;

    const uint32_t smbase = smem_u32(smem);
    const uint32_t a_hi_lane = smbase + HHI_OFF + (lane & 15) * LDH_B + (lane >> 4) * 16;
    const uint32_t a_lo_lane = smbase + HLO_OFF + (lane & 15) * LDH_B + (lane >> 4) * 16;

    const int wfoff = (4 * nw) * 32 + lane;     // B fragment base offset for this warp

    // attention / staging mapping: thread owns (row, 32-col group qg)
    const int row = tid >> 2;
    const int qg  = tid & 3;                    // head = qg>>1, half = qg&1
    const int c0  = 32 * qg;

    // ---- stage H = x + PE ----
    {
        const float* xb = x + (size_t)bi * 8388608 + (size_t)t * 128;
        float v[32];
#pragma unroll
        for (int c = 0; c < 32; c++)
            v[c] = xb[(size_t)(c0 + c) * 65536 + row] + g_pe[(c0 + c) * 128 + row];
        stage_rowvals(v, smem, row, c0);
    }

    const int deltas[11] = {-124, -111, -96, -76, -48, 0, 48, 76, 96, 111, 124};
    float d[8][4];

#pragma unroll 1
    for (int l = 0; l < 4; l++) {
        __syncthreads();                                     // H staged/visible

        gemm_mma(a_hi_lane, a_lo_lane, g_wfrag + (4*l + 0) * 4096 + wfoff, mw, d);
        epi_h16(d, Kh, bk + l * 128, mw, nw, lane);
        gemm_mma(a_hi_lane, a_lo_lane, g_wfrag + (4*l + 1) * 4096 + wfoff, mw, d);
        epi_h16(d, Vh, bv + l * 128, mw, nw, lane);
        gemm_mma(a_hi_lane, a_lo_lane, g_wfrag + (4*l + 2) * 4096 + wfoff, mw, d);
        __syncthreads();                                     // all H reads done
        epi_f32(d, Qs, bq + l * 128, mw, nw, lane, LDQ);     // Q overlays H region
        __syncthreads();                                     // Q/K/V visible

        // ---- sparse harmonic attention: thread owns (row, qg) ----
        float o[32];
        {
            float q[32];
            const float* qp = &Qs[row * LDQ + c0];
#pragma unroll
            for (int i = 0; i < 32; i++) q[i] = qp[i];

            float sv[11];
#pragma unroll
            for (int dd = 0; dd < 11; dd++) {
                int j = row + deltas[dd];
                bool valid = (unsigned)j < 128u;
                float a = 0.f;
                if (valid) {
                    const unsigned char* kb = Kh + j * LDKV_B + qg * 32;
#pragma unroll
                    for (int i = 0; i < 4; i++) {
                        uint4 raw = *(const uint4*)(kb + ((i & 1) << 7) + ((i >> 1) << 4));
                        const __half2* hp = (const __half2*)&raw;
#pragma unroll
                        for (int tp = 0; tp < 4; tp++) {
                            float2 f = __half22float2(hp[tp]);
                            a = fmaf(q[8*i + 2*tp],     f.x, a);
                            a = fmaf(q[8*i + 2*tp + 1], f.y, a);
                        }
                    }
                }
                a += __shfl_xor_sync(0xffffffffu, a, 1);     // combine head halves
                sv[dd] = valid ? a * 0.125f : -1e30f;        // 1/sqrt(64)
            }
            float m = sv[0];
#pragma unroll
            for (int dd = 1; dd < 11; dd++) m = fmaxf(m, sv[dd]);
            float sum = 0.f;
#pragma unroll
            for (int dd = 0; dd < 11; dd++) sum += __expf(sv[dd] - m);
            float inv = __fdividef(1.f, sum);
#pragma unroll
            for (int i = 0; i < 32; i++) o[i] = 0.f;
#pragma unroll
            for (int dd = 0; dd < 11; dd++) {
                int j = row + deltas[dd];
                if ((unsigned)j < 128u) {
                    float wj = __expf(sv[dd] - m) * inv;
                    const unsigned char* vb = Vh + j * LDKV_B + qg * 32;
#pragma unroll
                    for (int i = 0; i < 4; i++) {
                        uint4 raw = *(const uint4*)(vb + ((i & 1) << 7) + ((i >> 1) << 4));
                        const __half2* hp = (const __half2*)&raw;
#pragma unroll
                        for (int tp = 0; tp < 4; tp++) {
                            float2 f = __half22float2(hp[tp]);
                            o[8*i + 2*tp]     = fmaf(wj, f.x, o[8*i + 2*tp]);
                            o[8*i + 2*tp + 1] = fmaf(wj, f.y, o[8*i + 2*tp + 1]);
                        }
                    }
                }
            }
        }
        __syncthreads();                                     // all Q reads done
        stage_rowvals(o, smem, row, c0);                     // O -> H buffers
        __syncthreads();                                     // O staged

        gemm_mma(a_hi_lane, a_lo_lane, g_wfrag + (4*l + 3) * 4096 + wfoff, mw, d);
        __syncthreads();                                     // all O reads done
        if (l < 3) {
            epi_f16(d, smem, bo + l * 128, mw, nw, lane);    // H_new staged
        } else {
            float* ob = out + (size_t)bi * 8388608 + (size_t)t * 128;
            epi_out(d, ob, bo + l * 128, mw, nw, lane);
        }
    }
}

extern "C" void kernel_launch(void* const* d_in, const int* in_sizes, int n_in,
                              void* d_out, int out_size)
{
    const float* x  = (const float*)d_in[0];
    const float* Wq = (const float*)d_in[1];
    const float* bq = (const float*)d_in[2];
    const float* Wk = (const float*)d_in[3];
    const float* bk = (const float*)d_in[4];
    const float* Wv = (const float*)d_in[5];
    const float* bv = (const float*)d_in[6];
    const float* Wo = (const float*)d_in[7];
    const float* bo = (const float*)d_in[8];
    float* out = (float*)d_out;

    const int NB = in_sizes[0] / (128 * TT * 128);   // batch (4)

    prep_w<<<17, 256>>>(Wq, Wk, Wv, Wo);

    cudaFuncSetAttribute(hattn_mma, cudaFuncAttributeMaxDynamicSharedMemorySize, SMEM_TOTAL);
    hattn_mma<<<NB * TT, NTHREADS, SMEM_TOTAL>>>(x, bq, bk, bv, bo, out);
}

// round 14
// speedup vs baseline: 1.4849x; 1.0917x over previous
#include <cuda_runtime.h>
#include <cuda_fp16.h>
#include <cstdint>

// HarmonicAwaredAttention via warp-level HMMA (mma.sync, arch-agnostic PTX).
// R14: Q also fp16 chunk-interleaved (own buffer, no H overlay) -> 4 syncs/layer;
//      exp stored back into sv (halve MUFU); persistent blocks (grid=152).
// GEMMs: m16n8k16 fp16 MMA, 2-term split (Ah*B + Al*B), B single-rounded fp16.

#define TT 512
#define NTHREADS 512
#define LDH_B  272            // fp16 row stride in bytes (136 elems)
#define LDKV_B 272            // K/V/Q fp16 row stride in bytes

// smem byte offsets
#define HHI_OFF 0
#define HLO_OFF 34816
#define KS_OFF  69632          // fp16 K, 34816 bytes
#define VS_OFF  104448         // fp16 V, 34816 bytes
#define QS_OFF  139264         // fp16 Q, 34816 bytes (own buffer)
#define SMEM_TOTAL 174080

// weights, fragment-linear uint2 (fp16): [gemm][ks 0..7][j 0..15][lane 0..31]
__device__ __align__(16) uint2 g_wfrag[16 * 4096];
__device__ float g_pe[128 * 128];     // g_pe[c*128 + f]

__device__ __forceinline__ uint32_t smem_u32(const void* p) {
    uint32_t a;
    asm("{ .reg .u64 t; cvta.to.shared.u64 t, %1; cvt.u32.u64 %0, t; }" : "=r"(a) : "l"(p));
    return a;
}

#define LDSM(r, addr) \
    asm volatile("ldmatrix.sync.aligned.m8n8.x4.shared.b16 {%0,%1,%2,%3}, [%4];" \
        : "=r"((r)[0]), "=r"((r)[1]), "=r"((r)[2]), "=r"((r)[3]) : "r"(addr))

#define MMA(dp, a, bx, by) \
    asm volatile("mma.sync.aligned.m16n8k16.row.col.f32.f16.f16.f32 " \
        "{%0,%1,%2,%3},{%4,%5,%6,%7},{%8,%9},{%0,%1,%2,%3};" \
        : "+f"((dp)[0]), "+f"((dp)[1]), "+f"((dp)[2]), "+f"((dp)[3]) \
        : "r"((a)[0]), "r"((a)[1]), "r"((a)[2]), "r"((a)[3]), "r"(bx), "r"(by))

// K/V/Q fp16 layout: byte offset(r, C) = r*272 + (C>>5)*32 + ((i&1)<<7) + ((i>>1)<<4)
// + (C&7)*2, where i=(C&31)>>3. Conflict-free for the epilogue STS.32 and the
// per-thread 4x LDS.128 attention reads (validated R12/R13).

// ---------------- prologue: fragment-pack weights + PE table ----------------
__global__ void prep_w(const float* __restrict__ Wq, const float* __restrict__ Wk,
                       const float* __restrict__ Wv, const float* __restrict__ Wo)
{
    int g = blockIdx.x;
    if (g == 16) {   // PE table
        for (int idx = threadIdx.x; idx < 128 * 128; idx += blockDim.x) {
            int c = idx >> 7, f = idx & 127;
            float e     = (float)(c & ~1) * (1.0f / 128.0f);
            float denom = exp2f(e * 13.287712379549449f);   // 10000^(i/128)
            float ang   = (float)f / denom;
            g_pe[c * 128 + f] = (c & 1) ? cosf(ang) : sinf(ang);
        }
        return;
    }
    int l = g >> 2, m = g & 3;
    const float* src = (m == 0 ? Wk : m == 1 ? Wv : m == 2 ? Wq : Wo) + l * 16384;
    for (int e = threadIdx.x; e < 4096; e += blockDim.x) {
        int lane = e & 31, j = (e >> 5) & 15, ks = e >> 9;
        int n  = 8 * j + (lane >> 2);
        int k0 = 16 * ks + 2 * (lane & 3);
        float w00 = src[k0 * 128 + n],       w01 = src[(k0 + 1) * 128 + n];
        float w10 = src[(k0 + 8) * 128 + n], w11 = src[(k0 + 9) * 128 + n];
        __half2 h0 = __floats2half2_rn(w00, w01);
        __half2 h1 = __floats2half2_rn(w10, w11);
        uint2 o;
        o.x = *(uint32_t*)&h0;
        o.y = *(uint32_t*)&h1;
        g_wfrag[g * 4096 + e] = o;
    }
}

// ------------- GEMM: warp (mw,nw) computes D[32 rows x 32 cols] -------------
// Stage-pipelined: LDSM of next stage issued before MMAs of current stage.
__device__ __forceinline__ void gemm_mma(uint32_t a_hi_lane, uint32_t a_lo_lane,
                                         const uint2* __restrict__ wf,
                                         int mw, float (*d)[4])
{
#pragma unroll
    for (int i = 0; i < 8; i++) { d[i][0] = 0.f; d[i][1] = 0.f; d[i][2] = 0.f; d[i][3] = 0.f; }

    const uint32_t a_row = (uint32_t)(mw * 32) * LDH_B;

    uint32_t ah[2][4], al[2][4];           // [mt-buffer][frag]
    LDSM(ah[0], a_hi_lane + a_row);        // stage (ks=0, mt=0)
    LDSM(al[0], a_lo_lane + a_row);

    uint2 b[4];
#pragma unroll
    for (int jj = 0; jj < 4; jj++) b[jj] = __ldg(wf + jj * 32);

#pragma unroll
    for (int ks = 0; ks < 8; ks++) {
        // prefetch stage (ks, mt=1)
        {
            uint32_t off = a_row + (uint32_t)(16 * LDH_B) + (uint32_t)ks * 32;
            LDSM(ah[1], a_hi_lane + off);
            LDSM(al[1], a_lo_lane + off);
        }
        // prefetch B for ks+1 (wraps; harmless reload on last)
        uint2 nb[4];
        {
            const uint2* p = wf + (((ks + 1) & 7) * 512);
#pragma unroll
            for (int jj = 0; jj < 4; jj++) nb[jj] = __ldg(p + jj * 32);
        }
        // MMAs for (ks, mt=0)
#pragma unroll
        for (int jj = 0; jj < 4; jj++) {
            MMA(d[jj], ah[0], b[jj].x, b[jj].y);
            MMA(d[jj], al[0], b[jj].x, b[jj].y);
        }
        // prefetch stage (ks+1, mt=0)
        if (ks < 7) {
            uint32_t off = a_row + (uint32_t)(ks + 1) * 32;
            LDSM(ah[0], a_hi_lane + off);
            LDSM(al[0], a_lo_lane + off);
        }
        // MMAs for (ks, mt=1)
#pragma unroll
        for (int jj = 0; jj < 4; jj++) {
            MMA(d[4 + jj], ah[1], b[jj].x, b[jj].y);
            MMA(d[4 + jj], al[1], b[jj].x, b[jj].y);
        }
#pragma unroll
        for (int jj = 0; jj < 4; jj++) b[jj] = nb[jj];
    }
}

// D + bias -> fp16 smem (chunk-interleaved K/V/Q layout). STS.32, conflict-free.
__device__ __forceinline__ void epi_h16(float (*d)[4], unsigned char* vb,
                                        const float* bias, int mw, int nw, int lane)
{
    int rq = lane >> 2, cq = 2 * (lane & 3);
#pragma unroll
    for (int jj = 0; jj < 4; jj++) {
        int c = 32 * nw + 8 * jj + cq;
        float b0 = __ldg(&bias[c]), b1 = __ldg(&bias[c + 1]);
        int colpart = nw * 32 + ((jj & 1) << 7) + ((jj >> 1) << 4) + cq * 2;
#pragma unroll
        for (int mt = 0; mt < 2; mt++) {
            int r0 = 32 * mw + 16 * mt + rq;
            __half2 h0 = __floats2half2_rn(d[mt*4+jj][0] + b0, d[mt*4+jj][1] + b1);
            __half2 h1 = __floats2half2_rn(d[mt*4+jj][2] + b0, d[mt*4+jj][3] + b1);
            *(uint32_t*)(vb + r0 * LDKV_B + colpart)       = *(uint32_t*)&h0;
            *(uint32_t*)(vb + (r0 + 8) * LDKV_B + colpart) = *(uint32_t*)&h1;
        }
    }
}

// D + bias -> fp16 hi/lo H buffers
__device__ __forceinline__ void epi_f16(float (*d)[4], unsigned char* sm,
                                        const float* bias, int mw, int nw, int lane)
{
    int rq = lane >> 2, cq = 2 * (lane & 3);
#pragma unroll
    for (int jj = 0; jj < 4; jj++) {
        int c = 32 * nw + 8 * jj + cq;
        float b0 = __ldg(&bias[c]), b1 = __ldg(&bias[c + 1]);
#pragma unroll
        for (int mt = 0; mt < 2; mt++) {
            int r0 = 32 * mw + 16 * mt + rq;
#pragma unroll
            for (int hh = 0; hh < 2; hh++) {
                int r = r0 + 8 * hh;
                float v0 = d[mt*4+jj][2*hh]     + b0;
                float v1 = d[mt*4+jj][2*hh + 1] + b1;
                __half2 hi2 = __floats2half2_rn(v0, v1);
                float2 hf = __half22float2(hi2);
                __half2 lo2 = __floats2half2_rn(v0 - hf.x, v1 - hf.y);
                *(uint32_t*)(sm + HHI_OFF + r * LDH_B + c * 2) = *(uint32_t*)&hi2;
                *(uint32_t*)(sm + HLO_OFF + r * LDH_B + c * 2) = *(uint32_t*)&lo2;
            }
        }
    }
}

// D + bias -> gmem out (transposed: out[c][r], channel stride 65536)
__device__ __forceinline__ void epi_out(float (*d)[4], float* ob, const float* bias,
                                        int mw, int nw, int lane)
{
    int rq = lane >> 2, cq = 2 * (lane & 3);
#pragma unroll
    for (int jj = 0; jj < 4; jj++) {
        int c = 32 * nw + 8 * jj + cq;
        float b0 = __ldg(&bias[c]), b1 = __ldg(&bias[c + 1]);
#pragma unroll
        for (int mt = 0; mt < 2; mt++) {
            int r0 = 32 * mw + 16 * mt + rq;
            ob[(size_t)c * 65536 + r0]           = d[mt*4+jj][0] + b0;
            ob[(size_t)(c + 1) * 65536 + r0]     = d[mt*4+jj][1] + b1;
            ob[(size_t)c * 65536 + r0 + 8]       = d[mt*4+jj][2] + b0;
            ob[(size_t)(c + 1) * 65536 + r0 + 8] = d[mt*4+jj][3] + b1;
        }
    }
}

// 32 fp32 vals (one row, one 32-col group) -> fp16 hi/lo into H buffers
__device__ __forceinline__ void stage_rowvals(const float* v, unsigned char* sm,
                                              int row, int c0)
{
#pragma unroll
    for (int i = 0; i < 16; i++) {
        float a = v[2 * i], b = v[2 * i + 1];
        __half2 hi2 = __floats2half2_rn(a, b);
        float2 hf = __half22float2(hi2);
        __half2 lo2 = __floats2half2_rn(a - hf.x, b - hf.y);
        *(uint32_t*)(sm + HHI_OFF + row * LDH_B + (c0 + 2 * i) * 2) = *(uint32_t*)&hi2;
        *(uint32_t*)(sm + HLO_OFF + row * LDH_B + (c0 + 2 * i) * 2) = *(uint32_t*)&lo2;
    }
}

extern __shared__ unsigned char smem[];

__global__ void __launch_bounds__(NTHREADS, 1)
hattn_mma(const float* __restrict__ x,
          const float* __restrict__ bq, const float* __restrict__ bk,
          const float* __restrict__ bv, const float* __restrict__ bo,
          float* __restrict__ out, int nseq)
{
    const int tid = threadIdx.x;
    const int w = tid >> 5, lane = tid & 31;
    const int mw = w & 3, nw = w >> 2;          // warp grid 4(M) x 4(N)

    unsigned char* Kh = smem + KS_OFF;
    unsigned char* Vh = smem + VS_OFF;
    unsigned char* Qh = smem + QS_OFF;

    const uint32_t smbase = smem_u32(smem);
    const uint32_t a_hi_lane = smbase + HHI_OFF + (lane & 15) * LDH_B + (lane >> 4) * 16;
    const uint32_t a_lo_lane = smbase + HLO_OFF + (lane & 15) * LDH_B + (lane >> 4) * 16;

    const int wfoff = (4 * nw) * 32 + lane;     // B fragment base offset for this warp

    // attention / staging mapping: thread owns (row, 32-col group qg)
    const int row = tid >> 2;
    const int qg  = tid & 3;                    // head = qg>>1, half = qg&1
    const int c0  = 32 * qg;

    const int deltas[11] = {-124, -111, -96, -76, -48, 0, 48, 76, 96, 111, 124};
    float d[8][4];

    // persistent: each block walks sequences n = bid, bid+grid, ...
    for (int n = blockIdx.x; n < nseq; n += gridDim.x) {
        const int bi = n >> 9;                   // n / TT
        const int t  = n & (TT - 1);

        // ---- stage H = x + PE ----  (previous Wo-gemm reads synced below)
        {
            const float* xb = x + (size_t)bi * 8388608 + (size_t)t * 128;
            float v[32];
#pragma unroll
            for (int c = 0; c < 32; c++)
                v[c] = xb[(size_t)(c0 + c) * 65536 + row] + g_pe[(c0 + c) * 128 + row];
            stage_rowvals(v, smem, row, c0);
        }

#pragma unroll 1
        for (int l = 0; l < 4; l++) {
            __syncthreads();                                 // H staged/visible

            gemm_mma(a_hi_lane, a_lo_lane, g_wfrag + (4*l + 0) * 4096 + wfoff, mw, d);
            epi_h16(d, Kh, bk + l * 128, mw, nw, lane);
            gemm_mma(a_hi_lane, a_lo_lane, g_wfrag + (4*l + 1) * 4096 + wfoff, mw, d);
            epi_h16(d, Vh, bv + l * 128, mw, nw, lane);
            gemm_mma(a_hi_lane, a_lo_lane, g_wfrag + (4*l + 2) * 4096 + wfoff, mw, d);
            epi_h16(d, Qh, bq + l * 128, mw, nw, lane);      // Q own buffer, no sync
            __syncthreads();                                 // K/V/Q visible

            // ---- sparse harmonic attention: thread owns (row, qg) ----
            float o[32];
            {
                float q[32];
                {
                    const unsigned char* qb = Qh + row * LDKV_B + qg * 32;
#pragma unroll
                    for (int i = 0; i < 4; i++) {
                        uint4 raw = *(const uint4*)(qb + ((i & 1) << 7) + ((i >> 1) << 4));
                        const __half2* hp = (const __half2*)&raw;
#pragma unroll
                        for (int tp = 0; tp < 4; tp++) {
                            float2 f = __half22float2(hp[tp]);
                            q[8*i + 2*tp]     = f.x;
                            q[8*i + 2*tp + 1] = f.y;
                        }
                    }
                }

                float sv[11];
#pragma unroll
                for (int dd = 0; dd < 11; dd++) {
                    int j = row + deltas[dd];
                    bool valid = (unsigned)j < 128u;
                    float a = 0.f;
                    if (valid) {
                        const unsigned char* kb = Kh + j * LDKV_B + qg * 32;
#pragma unroll
                        for (int i = 0; i < 4; i++) {
                            uint4 raw = *(const uint4*)(kb + ((i & 1) << 7) + ((i >> 1) << 4));
                            const __half2* hp = (const __half2*)&raw;
#pragma unroll
                            for (int tp = 0; tp < 4; tp++) {
                                float2 f = __half22float2(hp[tp]);
                                a = fmaf(q[8*i + 2*tp],     f.x, a);
                                a = fmaf(q[8*i + 2*tp + 1], f.y, a);
                            }
                        }
                    }
                    a += __shfl_xor_sync(0xffffffffu, a, 1); // combine head halves
                    sv[dd] = valid ? a * 0.125f : -1e30f;    // 1/sqrt(64)
                }
                float m = sv[0];
#pragma unroll
                for (int dd = 1; dd < 11; dd++) m = fmaxf(m, sv[dd]);
                float sum = 0.f;
#pragma unroll
                for (int dd = 0; dd < 11; dd++) {
                    float e = __expf(sv[dd] - m);
                    sv[dd] = e;                              // reuse: exp once
                    sum += e;
                }
                float inv = __fdividef(1.f, sum);
#pragma unroll
                for (int i = 0; i < 32; i++) o[i] = 0.f;
#pragma unroll
                for (int dd = 0; dd < 11; dd++) {
                    int j = row + deltas[dd];
                    if ((unsigned)j < 128u) {
                        float wj = sv[dd] * inv;
                        const unsigned char* vb = Vh + j * LDKV_B + qg * 32;
#pragma unroll
                        for (int i = 0; i < 4; i++) {
                            uint4 raw = *(const uint4*)(vb + ((i & 1) << 7) + ((i >> 1) << 4));
                            const __half2* hp = (const __half2*)&raw;
#pragma unroll
                            for (int tp = 0; tp < 4; tp++) {
                                float2 f = __half22float2(hp[tp]);
                                o[8*i + 2*tp]     = fmaf(wj, f.x, o[8*i + 2*tp]);
                                o[8*i + 2*tp + 1] = fmaf(wj, f.y, o[8*i + 2*tp + 1]);
                            }
                        }
                    }
                }
            }
            // H's last reader (Q gemm) completed before the pre-attention sync;
            // safe to overwrite H with O now (per-thread disjoint rows).
            stage_rowvals(o, smem, row, c0);                 // O -> H buffers
            __syncthreads();                                 // O staged

            gemm_mma(a_hi_lane, a_lo_lane, g_wfrag + (4*l + 3) * 4096 + wfoff, mw, d);
            __syncthreads();                                 // all O reads done
            if (l < 3) {
                epi_f16(d, smem, bo + l * 128, mw, nw, lane); // H_new staged
            } else {
                float* ob = out + (size_t)bi * 8388608 + (size_t)t * 128;
                epi_out(d, ob, bo + l * 128, mw, nw, lane);
            }
        }
    }
}

extern "C" void kernel_launch(void* const* d_in, const int* in_sizes, int n_in,
                              void* d_out, int out_size)
{
    const float* x  = (const float*)d_in[0];
    const float* Wq = (const float*)d_in[1];
    const float* bq = (const float*)d_in[2];
    const float* Wk = (const float*)d_in[3];
    const float* bk = (const float*)d_in[4];
    const float* Wv = (const float*)d_in[5];
    const float* bv = (const float*)d_in[6];
    const float* Wo = (const float*)d_in[7];
    const float* bo = (const float*)d_in[8];
    float* out = (float*)d_out;

    const int NB = in_sizes[0] / (128 * TT * 128);   // batch (4)
    const int nseq = NB * TT;

    prep_w<<<17, 256>>>(Wq, Wk, Wv, Wo);

    cudaFuncSetAttribute(hattn_mma, cudaFuncAttributeMaxDynamicSharedMemorySize, SMEM_TOTAL);
    int grid = 152;                                  // GB300 SM count; 1 CTA/SM
    if (grid > nseq) grid = nseq;
    hattn_mma<<<grid, NTHREADS, SMEM_TOTAL>>>(x, bq, bk, bv, bo, out, nseq);
}

// round 15
// speedup vs baseline: 1.8660x; 1.2567x over previous
#include <cuda_runtime.h>
#include <cuda_fp16.h>
#include <cstdint>

// HarmonicAwaredAttention via warp-level HMMA (mma.sync, arch-agnostic PTX).
// R15: H stored plain fp16 (no lo buffer) -> K/V/Q GEMMs single-term
//      (A-rounding error class measured cheap in R12-R14). O keeps hi/lo split;
//      Wo GEMM stays 2-term (its output compounds across layers).
// Persistent grid (152), 512 threads, warp grid 4(M)x4(N).

#define TT 512
#define NTHREADS 512
#define LDH_B  272            // fp16 row stride in bytes (136 elems)
#define LDKV_B 272            // K/V/Q fp16 row stride in bytes

// smem byte offsets
#define HHI_OFF 0              // fp16 H (and O-hi after attention)
#define OLO_OFF 34816          // fp16 O-lo (Wo gemm 2nd term)
#define KS_OFF  69632          // fp16 K
#define VS_OFF  104448         // fp16 V
#define QS_OFF  139264         // fp16 Q
#define SMEM_TOTAL 174080

// weights, fragment-linear uint2 (fp16): [gemm][ks 0..7][j 0..15][lane 0..31]
__device__ __align__(16) uint2 g_wfrag[16 * 4096];
__device__ float g_pe[128 * 128];     // g_pe[c*128 + f]

__device__ __forceinline__ uint32_t smem_u32(const void* p) {
    uint32_t a;
    asm("{ .reg .u64 t; cvta.to.shared.u64 t, %1; cvt.u32.u64 %0, t; }" : "=r"(a) : "l"(p));
    return a;
}

#define LDSM(r, addr) \
    asm volatile("ldmatrix.sync.aligned.m8n8.x4.shared.b16 {%0,%1,%2,%3}, [%4];" \
        : "=r"((r)[0]), "=r"((r)[1]), "=r"((r)[2]), "=r"((r)[3]) : "r"(addr))

#define MMA(dp, a, bx, by) \
    asm volatile("mma.sync.aligned.m16n8k16.row.col.f32.f16.f16.f32 " \
        "{%0,%1,%2,%3},{%4,%5,%6,%7},{%8,%9},{%0,%1,%2,%3};" \
        : "+f"((dp)[0]), "+f"((dp)[1]), "+f"((dp)[2]), "+f"((dp)[3]) \
        : "r"((a)[0]), "r"((a)[1]), "r"((a)[2]), "r"((a)[3]), "r"(bx), "r"(by))

// K/V/Q fp16 layout: byte offset(r, C) = r*272 + (C>>5)*32 + ((i&1)<<7) + ((i>>1)<<4)
// + (C&7)*2, where i=(C&31)>>3. Conflict-free STS.32 epilogue + LDS.128 attention
// reads (validated R12-R14).

// ---------------- prologue: fragment-pack weights + PE table ----------------
__global__ void prep_w(const float* __restrict__ Wq, const float* __restrict__ Wk,
                       const float* __restrict__ Wv, const float* __restrict__ Wo)
{
    int g = blockIdx.x;
    if (g == 16) {   // PE table
        for (int idx = threadIdx.x; idx < 128 * 128; idx += blockDim.x) {
            int c = idx >> 7, f = idx & 127;
            float e     = (float)(c & ~1) * (1.0f / 128.0f);
            float denom = exp2f(e * 13.287712379549449f);   // 10000^(i/128)
            float ang   = (float)f / denom;
            g_pe[c * 128 + f] = (c & 1) ? cosf(ang) : sinf(ang);
        }
        return;
    }
    int l = g >> 2, m = g & 3;
    const float* src = (m == 0 ? Wk : m == 1 ? Wv : m == 2 ? Wq : Wo) + l * 16384;
    for (int e = threadIdx.x; e < 4096; e += blockDim.x) {
        int lane = e & 31, j = (e >> 5) & 15, ks = e >> 9;
        int n  = 8 * j + (lane >> 2);
        int k0 = 16 * ks + 2 * (lane & 3);
        float w00 = src[k0 * 128 + n],       w01 = src[(k0 + 1) * 128 + n];
        float w10 = src[(k0 + 8) * 128 + n], w11 = src[(k0 + 9) * 128 + n];
        __half2 h0 = __floats2half2_rn(w00, w01);
        __half2 h1 = __floats2half2_rn(w10, w11);
        uint2 o;
        o.x = *(uint32_t*)&h0;
        o.y = *(uint32_t*)&h1;
        g_wfrag[g * 4096 + e] = o;
    }
}

// ---- single-term GEMM (K/V/Q): D = A(fp16) @ B^T, warp tile 32x32 ----
__device__ __forceinline__ void gemm1(uint32_t a_lane, const uint2* __restrict__ wf,
                                      int mw, float (*d)[4])
{
#pragma unroll
    for (int i = 0; i < 8; i++) { d[i][0] = 0.f; d[i][1] = 0.f; d[i][2] = 0.f; d[i][3] = 0.f; }

    const uint32_t a_row = (uint32_t)(mw * 32) * LDH_B;

    uint32_t ah[2][4];
    LDSM(ah[0], a_lane + a_row);           // stage (ks=0, mt=0)

    uint2 b[4];
#pragma unroll
    for (int jj = 0; jj < 4; jj++) b[jj] = __ldg(wf + jj * 32);

#pragma unroll
    for (int ks = 0; ks < 8; ks++) {
        LDSM(ah[1], a_lane + a_row + (uint32_t)(16 * LDH_B) + (uint32_t)ks * 32);
        uint2 nb[4];
        {
            const uint2* p = wf + (((ks + 1) & 7) * 512);
#pragma unroll
            for (int jj = 0; jj < 4; jj++) nb[jj] = __ldg(p + jj * 32);
        }
#pragma unroll
        for (int jj = 0; jj < 4; jj++) MMA(d[jj], ah[0], b[jj].x, b[jj].y);
        if (ks < 7)
            LDSM(ah[0], a_lane + a_row + (uint32_t)(ks + 1) * 32);
#pragma unroll
        for (int jj = 0; jj < 4; jj++) MMA(d[4 + jj], ah[1], b[jj].x, b[jj].y);
#pragma unroll
        for (int jj = 0; jj < 4; jj++) b[jj] = nb[jj];
    }
}

// ---- 2-term GEMM (Wo): D = Ahi@B + Alo@B, stage-pipelined ----
__device__ __forceinline__ void gemm2(uint32_t a_hi_lane, uint32_t a_lo_lane,
                                      const uint2* __restrict__ wf,
                                      int mw, float (*d)[4])
{
#pragma unroll
    for (int i = 0; i < 8; i++) { d[i][0] = 0.f; d[i][1] = 0.f; d[i][2] = 0.f; d[i][3] = 0.f; }

    const uint32_t a_row = (uint32_t)(mw * 32) * LDH_B;

    uint32_t ah[2][4], al[2][4];
    LDSM(ah[0], a_hi_lane + a_row);
    LDSM(al[0], a_lo_lane + a_row);

    uint2 b[4];
#pragma unroll
    for (int jj = 0; jj < 4; jj++) b[jj] = __ldg(wf + jj * 32);

#pragma unroll
    for (int ks = 0; ks < 8; ks++) {
        {
            uint32_t off = a_row + (uint32_t)(16 * LDH_B) + (uint32_t)ks * 32;
            LDSM(ah[1], a_hi_lane + off);
            LDSM(al[1], a_lo_lane + off);
        }
        uint2 nb[4];
        {
            const uint2* p = wf + (((ks + 1) & 7) * 512);
#pragma unroll
            for (int jj = 0; jj < 4; jj++) nb[jj] = __ldg(p + jj * 32);
        }
#pragma unroll
        for (int jj = 0; jj < 4; jj++) {
            MMA(d[jj], ah[0], b[jj].x, b[jj].y);
            MMA(d[jj], al[0], b[jj].x, b[jj].y);
        }
        if (ks < 7) {
            uint32_t off = a_row + (uint32_t)(ks + 1) * 32;
            LDSM(ah[0], a_hi_lane + off);
            LDSM(al[0], a_lo_lane + off);
        }
#pragma unroll
        for (int jj = 0; jj < 4; jj++) {
            MMA(d[4 + jj], ah[1], b[jj].x, b[jj].y);
            MMA(d[4 + jj], al[1], b[jj].x, b[jj].y);
        }
#pragma unroll
        for (int jj = 0; jj < 4; jj++) b[jj] = nb[jj];
    }
}

// D + bias -> fp16 smem (chunk-interleaved K/V/Q layout). STS.32, conflict-free.
__device__ __forceinline__ void epi_h16(float (*d)[4], unsigned char* vb,
                                        const float* bias, int mw, int nw, int lane)
{
    int rq = lane >> 2, cq = 2 * (lane & 3);
#pragma unroll
    for (int jj = 0; jj < 4; jj++) {
        int c = 32 * nw + 8 * jj + cq;
        float b0 = __ldg(&bias[c]), b1 = __ldg(&bias[c + 1]);
        int colpart = nw * 32 + ((jj & 1) << 7) + ((jj >> 1) << 4) + cq * 2;
#pragma unroll
        for (int mt = 0; mt < 2; mt++) {
            int r0 = 32 * mw + 16 * mt + rq;
            __half2 h0 = __floats2half2_rn(d[mt*4+jj][0] + b0, d[mt*4+jj][1] + b1);
            __half2 h1 = __floats2half2_rn(d[mt*4+jj][2] + b0, d[mt*4+jj][3] + b1);
            *(uint32_t*)(vb + r0 * LDKV_B + colpart)       = *(uint32_t*)&h0;
            *(uint32_t*)(vb + (r0 + 8) * LDKV_B + colpart) = *(uint32_t*)&h1;
        }
    }
}

// D + bias -> plain fp16 H buffer (row-linear, LDSM layout)
__device__ __forceinline__ void epi_hnew(float (*d)[4], unsigned char* sm,
                                         const float* bias, int mw, int nw, int lane)
{
    int rq = lane >> 2, cq = 2 * (lane & 3);
#pragma unroll
    for (int jj = 0; jj < 4; jj++) {
        int c = 32 * nw + 8 * jj + cq;
        float b0 = __ldg(&bias[c]), b1 = __ldg(&bias[c + 1]);
#pragma unroll
        for (int mt = 0; mt < 2; mt++) {
            int r0 = 32 * mw + 16 * mt + rq;
#pragma unroll
            for (int hh = 0; hh < 2; hh++) {
                int r = r0 + 8 * hh;
                float v0 = d[mt*4+jj][2*hh]     + b0;
                float v1 = d[mt*4+jj][2*hh + 1] + b1;
                __half2 hi2 = __floats2half2_rn(v0, v1);
                *(uint32_t*)(sm + HHI_OFF + r * LDH_B + c * 2) = *(uint32_t*)&hi2;
            }
        }
    }
}

// D + bias -> gmem out (transposed: out[c][r], channel stride 65536)
__device__ __forceinline__ void epi_out(float (*d)[4], float* ob, const float* bias,
                                        int mw, int nw, int lane)
{
    int rq = lane >> 2, cq = 2 * (lane & 3);
#pragma unroll
    for (int jj = 0; jj < 4; jj++) {
        int c = 32 * nw + 8 * jj + cq;
        float b0 = __ldg(&bias[c]), b1 = __ldg(&bias[c + 1]);
#pragma unroll
        for (int mt = 0; mt < 2; mt++) {
            int r0 = 32 * mw + 16 * mt + rq;
            ob[(size_t)c * 65536 + r0]           = d[mt*4+jj][0] + b0;
            ob[(size_t)(c + 1) * 65536 + r0]     = d[mt*4+jj][1] + b1;
            ob[(size_t)c * 65536 + r0 + 8]       = d[mt*4+jj][2] + b0;
            ob[(size_t)(c + 1) * 65536 + r0 + 8] = d[mt*4+jj][3] + b1;
        }
    }
}

// 32 fp32 vals (one row, one 32-col group) -> plain fp16 H buffer
__device__ __forceinline__ void stage_x(const float* v, unsigned char* sm,
                                        int row, int c0)
{
#pragma unroll
    for (int i = 0; i < 16; i++) {
        __half2 hi2 = __floats2half2_rn(v[2 * i], v[2 * i + 1]);
        *(uint32_t*)(sm + HHI_OFF + row * LDH_B + (c0 + 2 * i) * 2) = *(uint32_t*)&hi2;
    }
}

// 32 fp32 vals -> fp16 hi (H buffer) + lo (OLO buffer) for the 2-term Wo gemm
__device__ __forceinline__ void stage_o(const float* v, unsigned char* sm,
                                        int row, int c0)
{
#pragma unroll
    for (int i = 0; i < 16; i++) {
        float a = v[2 * i], b = v[2 * i + 1];
        __half2 hi2 = __floats2half2_rn(a, b);
        float2 hf = __half22float2(hi2);
        __half2 lo2 = __floats2half2_rn(a - hf.x, b - hf.y);
        *(uint32_t*)(sm + HHI_OFF + row * LDH_B + (c0 + 2 * i) * 2) = *(uint32_t*)&hi2;
        *(uint32_t*)(sm + OLO_OFF + row * LDH_B + (c0 + 2 * i) * 2) = *(uint32_t*)&lo2;
    }
}

extern __shared__ unsigned char smem[];

__global__ void __launch_bounds__(NTHREADS, 1)
hattn_mma(const float* __restrict__ x,
          const float* __restrict__ bq, const float* __restrict__ bk,
          const float* __restrict__ bv, const float* __restrict__ bo,
          float* __restrict__ out, int nseq)
{
    const int tid = threadIdx.x;
    const int w = tid >> 5, lane = tid & 31;
    const int mw = w & 3, nw = w >> 2;          // warp grid 4(M) x 4(N)

    unsigned char* Kh = smem + KS_OFF;
    unsigned char* Vh = smem + VS_OFF;
    unsigned char* Qh = smem + QS_OFF;

    const uint32_t smbase = smem_u32(smem);
    const uint32_t lane_off = (lane & 15) * LDH_B + (lane >> 4) * 16;
    const uint32_t a_hi_lane = smbase + HHI_OFF + lane_off;
    const uint32_t a_lo_lane = smbase + OLO_OFF + lane_off;

    const int wfoff = (4 * nw) * 32 + lane;     // B fragment base offset for this warp

    // attention / staging mapping: thread owns (row, 32-col group qg)
    const int row = tid >> 2;
    const int qg  = tid & 3;                    // head = qg>>1, half = qg&1
    const int c0  = 32 * qg;

    const int deltas[11] = {-124, -111, -96, -76, -48, 0, 48, 76, 96, 111, 124};
    float d[8][4];

    // persistent: each block walks sequences n = bid, bid+grid, ...
    for (int n = blockIdx.x; n < nseq; n += gridDim.x) {
        const int bi = n >> 9;                   // n / TT
        const int t  = n & (TT - 1);

        // ---- stage H = x + PE (plain fp16) ----
        {
            const float* xb = x + (size_t)bi * 8388608 + (size_t)t * 128;
            float v[32];
#pragma unroll
            for (int c = 0; c < 32; c++)
                v[c] = xb[(size_t)(c0 + c) * 65536 + row] + g_pe[(c0 + c) * 128 + row];
            stage_x(v, smem, row, c0);
        }

#pragma unroll 1
        for (int l = 0; l < 4; l++) {
            __syncthreads();                                 // H staged/visible

            gemm1(a_hi_lane, g_wfrag + (4*l + 0) * 4096 + wfoff, mw, d);
            epi_h16(d, Kh, bk + l * 128, mw, nw, lane);
            gemm1(a_hi_lane, g_wfrag + (4*l + 1) * 4096 + wfoff, mw, d);
            epi_h16(d, Vh, bv + l * 128, mw, nw, lane);
            gemm1(a_hi_lane, g_wfrag + (4*l + 2) * 4096 + wfoff, mw, d);
            epi_h16(d, Qh, bq + l * 128, mw, nw, lane);      // Q own buffer
            __syncthreads();                                 // K/V/Q visible

            // ---- sparse harmonic attention: thread owns (row, qg) ----
            float o[32];
            {
                float q[32];
                {
                    const unsigned char* qb = Qh + row * LDKV_B + qg * 32;
#pragma unroll
                    for (int i = 0; i < 4; i++) {
                        uint4 raw = *(const uint4*)(qb + ((i & 1) << 7) + ((i >> 1) << 4));
                        const __half2* hp = (const __half2*)&raw;
#pragma unroll
                        for (int tp = 0; tp < 4; tp++) {
                            float2 f = __half22float2(hp[tp]);
                            q[8*i + 2*tp]     = f.x;
                            q[8*i + 2*tp + 1] = f.y;
                        }
                    }
                }

                float sv[11];
#pragma unroll
                for (int dd = 0; dd < 11; dd++) {
                    int j = row + deltas[dd];
                    bool valid = (unsigned)j < 128u;
                    float a = 0.f;
                    if (valid) {
                        const unsigned char* kb = Kh + j * LDKV_B + qg * 32;
#pragma unroll
                        for (int i = 0; i < 4; i++) {
                            uint4 raw = *(const uint4*)(kb + ((i & 1) << 7) + ((i >> 1) << 4));
                            const __half2* hp = (const __half2*)&raw;
#pragma unroll
                            for (int tp = 0; tp < 4; tp++) {
                                float2 f = __half22float2(hp[tp]);
                                a = fmaf(q[8*i + 2*tp],     f.x, a);
                                a = fmaf(q[8*i + 2*tp + 1], f.y, a);
                            }
                        }
                    }
                    a += __shfl_xor_sync(0xffffffffu, a, 1); // combine head halves
                    sv[dd] = valid ? a * 0.125f : -1e30f;    // 1/sqrt(64)
                }
                float m = sv[0];
#pragma unroll
                for (int dd = 1; dd < 11; dd++) m = fmaxf(m, sv[dd]);
                float sum = 0.f;
#pragma unroll
                for (int dd = 0; dd < 11; dd++) {
                    float e = __expf(sv[dd] - m);
                    sv[dd] = e;                              // reuse: exp once
                    sum += e;
                }
                float inv = __fdividef(1.f, sum);
#pragma unroll
                for (int i = 0; i < 32; i++) o[i] = 0.f;
#pragma unroll
                for (int dd = 0; dd < 11; dd++) {
                    int j = row + deltas[dd];
                    if ((unsigned)j < 128u) {
                        float wj = sv[dd] * inv;
                        const unsigned char* vb = Vh + j * LDKV_B + qg * 32;
#pragma unroll
                        for (int i = 0; i < 4; i++) {
                            uint4 raw = *(const uint4*)(vb + ((i & 1) << 7) + ((i >> 1) << 4));
                            const __half2* hp = (const __half2*)&raw;
#pragma unroll
                            for (int tp = 0; tp < 4; tp++) {
                                float2 f = __half22float2(hp[tp]);
                                o[8*i + 2*tp]     = fmaf(wj, f.x, o[8*i + 2*tp]);
                                o[8*i + 2*tp + 1] = fmaf(wj, f.y, o[8*i + 2*tp + 1]);
                            }
                        }
                    }
                }
            }
            // H's last reader (Q gemm) done before the K/V/Q sync; OLO's last
            // reader (prev Wo gemm) done two syncs ago -> safe to overwrite.
            stage_o(o, smem, row, c0);                       // O -> Hhi + OLO
            __syncthreads();                                 // O staged

            gemm2(a_hi_lane, a_lo_lane, g_wfrag + (4*l + 3) * 4096 + wfoff, mw, d);
            __syncthreads();                                 // all O reads done
            if (l < 3) {
                epi_hnew(d, smem, bo + l * 128, mw, nw, lane); // H_new (fp16)
            } else {
                float* ob = out + (size_t)bi * 8388608 + (size_t)t * 128;
                epi_out(d, ob, bo + l * 128, mw, nw, lane);
            }
        }
    }
}

extern "C" void kernel_launch(void* const* d_in, const int* in_sizes, int n_in,
                              void* d_out, int out_size)
{
    const float* x  = (const float*)d_in[0];
    const float* Wq = (const float*)d_in[1];
    const float* bq = (const float*)d_in[2];
    const float* Wk = (const float*)d_in[3];
    const float* bk = (const float*)d_in[4];
    const float* Wv = (const float*)d_in[5];
    const float* bv = (const float*)d_in[6];
    const float* Wo = (const float*)d_in[7];
    const float* bo = (const float*)d_in[8];
    float* out = (float*)d_out;

    const int NB = in_sizes[0] / (128 * TT * 128);   // batch (4)
    const int nseq = NB * TT;

    prep_w<<<17, 256>>>(Wq, Wk, Wv, Wo);

    cudaFuncSetAttribute(hattn_mma, cudaFuncAttributeMaxDynamicSharedMemorySize, SMEM_TOTAL);
    int grid = 152;                                  // GB300 SM count; 1 CTA/SM
    if (grid > nseq) grid = nseq;
    hattn_mma<<<grid, NTHREADS, SMEM_TOTAL>>>(x, bq, bk, bv, bo, out, nseq);
}

// round 16
// speedup vs baseline: 2.0826x; 1.1160x over previous
#include <cuda_runtime.h>
#include <cuda_fp16.h>
#include <cstdint>

// HarmonicAwaredAttention via warp-level HMMA (mma.sync, arch-agnostic PTX).
// R16: ALL GEMMs single-term fp16 (Wo's A-lo dropped: H_new is fp16-rounded at
//      every layer boundary anyway, so rounding O adds one ε of the same class).
//      Persistent grid (152), 512 threads, warp grid 4(M)x4(N), tile 32x32.

#define TT 512
#define NTHREADS 512
#define LDH_B  272            // fp16 row stride in bytes (136 elems)
#define LDKV_B 272            // K/V/Q fp16 row stride in bytes

// smem byte offsets
#define HHI_OFF 0              // fp16 H (and O after attention)
#define KS_OFF  34816          // fp16 K
#define VS_OFF  69632          // fp16 V
#define QS_OFF  104448         // fp16 Q
#define SMEM_TOTAL 139264

// weights, fragment-linear uint2 (fp16): [gemm][ks 0..7][j 0..15][lane 0..31]
__device__ __align__(16) uint2 g_wfrag[16 * 4096];
__device__ float g_pe[128 * 128];     // g_pe[c*128 + f]

__device__ __forceinline__ uint32_t smem_u32(const void* p) {
    uint32_t a;
    asm("{ .reg .u64 t; cvta.to.shared.u64 t, %1; cvt.u32.u64 %0, t; }" : "=r"(a) : "l"(p));
    return a;
}

#define LDSM(r, addr) \
    asm volatile("ldmatrix.sync.aligned.m8n8.x4.shared.b16 {%0,%1,%2,%3}, [%4];" \
        : "=r"((r)[0]), "=r"((r)[1]), "=r"((r)[2]), "=r"((r)[3]) : "r"(addr))

#define MMA(dp, a, bx, by) \
    asm volatile("mma.sync.aligned.m16n8k16.row.col.f32.f16.f16.f32 " \
        "{%0,%1,%2,%3},{%4,%5,%6,%7},{%8,%9},{%0,%1,%2,%3};" \
        : "+f"((dp)[0]), "+f"((dp)[1]), "+f"((dp)[2]), "+f"((dp)[3]) \
        : "r"((a)[0]), "r"((a)[1]), "r"((a)[2]), "r"((a)[3]), "r"(bx), "r"(by))

// K/V/Q fp16 layout: byte offset(r, C) = r*272 + (C>>5)*32 + ((i&1)<<7) + ((i>>1)<<4)
// + (C&7)*2, where i=(C&31)>>3. Conflict-free STS.32 epilogue + LDS.128 attention
// reads (validated R12-R15).

// ---------------- prologue: fragment-pack weights + PE table ----------------
__global__ void prep_w(const float* __restrict__ Wq, const float* __restrict__ Wk,
                       const float* __restrict__ Wv, const float* __restrict__ Wo)
{
    int g = blockIdx.x;
    if (g == 16) {   // PE table
        for (int idx = threadIdx.x; idx < 128 * 128; idx += blockDim.x) {
            int c = idx >> 7, f = idx & 127;
            float e     = (float)(c & ~1) * (1.0f / 128.0f);
            float denom = exp2f(e * 13.287712379549449f);   // 10000^(i/128)
            float ang   = (float)f / denom;
            g_pe[c * 128 + f] = (c & 1) ? cosf(ang) : sinf(ang);
        }
        return;
    }
    int l = g >> 2, m = g & 3;
    const float* src = (m == 0 ? Wk : m == 1 ? Wv : m == 2 ? Wq : Wo) + l * 16384;
    for (int e = threadIdx.x; e < 4096; e += blockDim.x) {
        int lane = e & 31, j = (e >> 5) & 15, ks = e >> 9;
        int n  = 8 * j + (lane >> 2);
        int k0 = 16 * ks + 2 * (lane & 3);
        float w00 = src[k0 * 128 + n],       w01 = src[(k0 + 1) * 128 + n];
        float w10 = src[(k0 + 8) * 128 + n], w11 = src[(k0 + 9) * 128 + n];
        __half2 h0 = __floats2half2_rn(w00, w01);
        __half2 h1 = __floats2half2_rn(w10, w11);
        uint2 o;
        o.x = *(uint32_t*)&h0;
        o.y = *(uint32_t*)&h1;
        g_wfrag[g * 4096 + e] = o;
    }
}

// ---- single-term GEMM: D = A(fp16) @ B^T, warp tile 32x32, stage-pipelined ----
__device__ __forceinline__ void gemm1(uint32_t a_lane, const uint2* __restrict__ wf,
                                      int mw, float (*d)[4])
{
#pragma unroll
    for (int i = 0; i < 8; i++) { d[i][0] = 0.f; d[i][1] = 0.f; d[i][2] = 0.f; d[i][3] = 0.f; }

    const uint32_t a_row = (uint32_t)(mw * 32) * LDH_B;

    uint32_t ah[2][4];
    LDSM(ah[0], a_lane + a_row);           // stage (ks=0, mt=0)

    uint2 b[4];
#pragma unroll
    for (int jj = 0; jj < 4; jj++) b[jj] = __ldg(wf + jj * 32);

#pragma unroll
    for (int ks = 0; ks < 8; ks++) {
        LDSM(ah[1], a_lane + a_row + (uint32_t)(16 * LDH_B) + (uint32_t)ks * 32);
        uint2 nb[4];
        {
            const uint2* p = wf + (((ks + 1) & 7) * 512);
#pragma unroll
            for (int jj = 0; jj < 4; jj++) nb[jj] = __ldg(p + jj * 32);
        }
#pragma unroll
        for (int jj = 0; jj < 4; jj++) MMA(d[jj], ah[0], b[jj].x, b[jj].y);
        if (ks < 7)
            LDSM(ah[0], a_lane + a_row + (uint32_t)(ks + 1) * 32);
#pragma unroll
        for (int jj = 0; jj < 4; jj++) MMA(d[4 + jj], ah[1], b[jj].x, b[jj].y);
#pragma unroll
        for (int jj = 0; jj < 4; jj++) b[jj] = nb[jj];
    }
}

// D + bias -> fp16 smem (chunk-interleaved K/V/Q layout). STS.32, conflict-free.
__device__ __forceinline__ void epi_h16(float (*d)[4], unsigned char* vb,
                                        const float* bias, int mw, int nw, int lane)
{
    int rq = lane >> 2, cq = 2 * (lane & 3);
#pragma unroll
    for (int jj = 0; jj < 4; jj++) {
        int c = 32 * nw + 8 * jj + cq;
        float b0 = __ldg(&bias[c]), b1 = __ldg(&bias[c + 1]);
        int colpart = nw * 32 + ((jj & 1) << 7) + ((jj >> 1) << 4) + cq * 2;
#pragma unroll
        for (int mt = 0; mt < 2; mt++) {
            int r0 = 32 * mw + 16 * mt + rq;
            __half2 h0 = __floats2half2_rn(d[mt*4+jj][0] + b0, d[mt*4+jj][1] + b1);
            __half2 h1 = __floats2half2_rn(d[mt*4+jj][2] + b0, d[mt*4+jj][3] + b1);
            *(uint32_t*)(vb + r0 * LDKV_B + colpart)       = *(uint32_t*)&h0;
            *(uint32_t*)(vb + (r0 + 8) * LDKV_B + colpart) = *(uint32_t*)&h1;
        }
    }
}

// D + bias -> plain fp16 H buffer (row-linear, LDSM layout)
__device__ __forceinline__ void epi_hnew(float (*d)[4], unsigned char* sm,
                                         const float* bias, int mw, int nw, int lane)
{
    int rq = lane >> 2, cq = 2 * (lane & 3);
#pragma unroll
    for (int jj = 0; jj < 4; jj++) {
        int c = 32 * nw + 8 * jj + cq;
        float b0 = __ldg(&bias[c]), b1 = __ldg(&bias[c + 1]);
#pragma unroll
        for (int mt = 0; mt < 2; mt++) {
            int r0 = 32 * mw + 16 * mt + rq;
#pragma unroll
            for (int hh = 0; hh < 2; hh++) {
                int r = r0 + 8 * hh;
                float v0 = d[mt*4+jj][2*hh]     + b0;
                float v1 = d[mt*4+jj][2*hh + 1] + b1;
                __half2 hi2 = __floats2half2_rn(v0, v1);
                *(uint32_t*)(sm + HHI_OFF + r * LDH_B + c * 2) = *(uint32_t*)&hi2;
            }
        }
    }
}

// D + bias -> gmem out (transposed: out[c][r], channel stride 65536)
__device__ __forceinline__ void epi_out(float (*d)[4], float* ob, const float* bias,
                                        int mw, int nw, int lane)
{
    int rq = lane >> 2, cq = 2 * (lane & 3);
#pragma unroll
    for (int jj = 0; jj < 4; jj++) {
        int c = 32 * nw + 8 * jj + cq;
        float b0 = __ldg(&bias[c]), b1 = __ldg(&bias[c + 1]);
#pragma unroll
        for (int mt = 0; mt < 2; mt++) {
            int r0 = 32 * mw + 16 * mt + rq;
            ob[(size_t)c * 65536 + r0]           = d[mt*4+jj][0] + b0;
            ob[(size_t)(c + 1) * 65536 + r0]     = d[mt*4+jj][1] + b1;
            ob[(size_t)c * 65536 + r0 + 8]       = d[mt*4+jj][2] + b0;
            ob[(size_t)(c + 1) * 65536 + r0 + 8] = d[mt*4+jj][3] + b1;
        }
    }
}

// 32 fp32 vals (one row, one 32-col group) -> plain fp16 H buffer
__device__ __forceinline__ void stage_x(const float* v, unsigned char* sm,
                                        int row, int c0)
{
#pragma unroll
    for (int i = 0; i < 16; i++) {
        __half2 hi2 = __floats2half2_rn(v[2 * i], v[2 * i + 1]);
        *(uint32_t*)(sm + HHI_OFF + row * LDH_B + (c0 + 2 * i) * 2) = *(uint32_t*)&hi2;
    }
}

extern __shared__ unsigned char smem[];

__global__ void __launch_bounds__(NTHREADS, 1)
hattn_mma(const float* __restrict__ x,
          const float* __restrict__ bq, const float* __restrict__ bk,
          const float* __restrict__ bv, const float* __restrict__ bo,
          float* __restrict__ out, int nseq)
{
    const int tid = threadIdx.x;
    const int w = tid >> 5, lane = tid & 31;
    const int mw = w & 3, nw = w >> 2;          // warp grid 4(M) x 4(N)

    unsigned char* Kh = smem + KS_OFF;
    unsigned char* Vh = smem + VS_OFF;
    unsigned char* Qh = smem + QS_OFF;

    const uint32_t smbase = smem_u32(smem);
    const uint32_t a_lane = smbase + HHI_OFF + (lane & 15) * LDH_B + (lane >> 4) * 16;

    const int wfoff = (4 * nw) * 32 + lane;     // B fragment base offset for this warp

    // attention / staging mapping: thread owns (row, 32-col group qg)
    const int row = tid >> 2;
    const int qg  = tid & 3;                    // head = qg>>1, half = qg&1
    const int c0  = 32 * qg;

    const int deltas[11] = {-124, -111, -96, -76, -48, 0, 48, 76, 96, 111, 124};
    float d[8][4];

    // persistent: each block walks sequences n = bid, bid+grid, ...
    for (int n = blockIdx.x; n < nseq; n += gridDim.x) {
        const int bi = n >> 9;                   // n / TT
        const int t  = n & (TT - 1);

        // ---- stage H = x + PE (plain fp16) ----
        {
            const float* xb = x + (size_t)bi * 8388608 + (size_t)t * 128;
            float v[32];
#pragma unroll
            for (int c = 0; c < 32; c++)
                v[c] = xb[(size_t)(c0 + c) * 65536 + row] + g_pe[(c0 + c) * 128 + row];
            stage_x(v, smem, row, c0);
        }

#pragma unroll 1
        for (int l = 0; l < 4; l++) {
            __syncthreads();                                 // H staged/visible

            gemm1(a_lane, g_wfrag + (4*l + 0) * 4096 + wfoff, mw, d);
            epi_h16(d, Kh, bk + l * 128, mw, nw, lane);
            gemm1(a_lane, g_wfrag + (4*l + 1) * 4096 + wfoff, mw, d);
            epi_h16(d, Vh, bv + l * 128, mw, nw, lane);
            gemm1(a_lane, g_wfrag + (4*l + 2) * 4096 + wfoff, mw, d);
            epi_h16(d, Qh, bq + l * 128, mw, nw, lane);      // Q own buffer
            __syncthreads();                                 // K/V/Q visible

            // ---- sparse harmonic attention: thread owns (row, qg) ----
            float o[32];
            {
                float q[32];
                {
                    const unsigned char* qb = Qh + row * LDKV_B + qg * 32;
#pragma unroll
                    for (int i = 0; i < 4; i++) {
                        uint4 raw = *(const uint4*)(qb + ((i & 1) << 7) + ((i >> 1) << 4));
                        const __half2* hp = (const __half2*)&raw;
#pragma unroll
                        for (int tp = 0; tp < 4; tp++) {
                            float2 f = __half22float2(hp[tp]);
                            q[8*i + 2*tp]     = f.x;
                            q[8*i + 2*tp + 1] = f.y;
                        }
                    }
                }

                float sv[11];
#pragma unroll
                for (int dd = 0; dd < 11; dd++) {
                    int j = row + deltas[dd];
                    bool valid = (unsigned)j < 128u;
                    float a = 0.f;
                    if (valid) {
                        const unsigned char* kb = Kh + j * LDKV_B + qg * 32;
#pragma unroll
                        for (int i = 0; i < 4; i++) {
                            uint4 raw = *(const uint4*)(kb + ((i & 1) << 7) + ((i >> 1) << 4));
                            const __half2* hp = (const __half2*)&raw;
#pragma unroll
                            for (int tp = 0; tp < 4; tp++) {
                                float2 f = __half22float2(hp[tp]);
                                a = fmaf(q[8*i + 2*tp],     f.x, a);
                                a = fmaf(q[8*i + 2*tp + 1], f.y, a);
                            }
                        }
                    }
                    a += __shfl_xor_sync(0xffffffffu, a, 1); // combine head halves
                    sv[dd] = valid ? a * 0.125f : -1e30f;    // 1/sqrt(64)
                }
                float m = sv[0];
#pragma unroll
                for (int dd = 1; dd < 11; dd++) m = fmaxf(m, sv[dd]);
                float sum = 0.f;
#pragma unroll
                for (int dd = 0; dd < 11; dd++) {
                    float e = __expf(sv[dd] - m);
                    sv[dd] = e;                              // reuse: exp once
                    sum += e;
                }
                float inv = __fdividef(1.f, sum);
#pragma unroll
                for (int i = 0; i < 32; i++) o[i] = 0.f;
#pragma unroll
                for (int dd = 0; dd < 11; dd++) {
                    int j = row + deltas[dd];
                    if ((unsigned)j < 128u) {
                        float wj = sv[dd] * inv;
                        const unsigned char* vb = Vh + j * LDKV_B + qg * 32;
#pragma unroll
                        for (int i = 0; i < 4; i++) {
                            uint4 raw = *(const uint4*)(vb + ((i & 1) << 7) + ((i >> 1) << 4));
                            const __half2* hp = (const __half2*)&raw;
#pragma unroll
                            for (int tp = 0; tp < 4; tp++) {
                                float2 f = __half22float2(hp[tp]);
                                o[8*i + 2*tp]     = fmaf(wj, f.x, o[8*i + 2*tp]);
                                o[8*i + 2*tp + 1] = fmaf(wj, f.y, o[8*i + 2*tp + 1]);
                            }
                        }
                    }
                }
            }
            // H's last reader (Q gemm) completed before the K/V/Q sync ->
            // safe to overwrite H with O (per-thread disjoint rows).
            stage_x(o, smem, row, c0);                       // O -> H buffer (fp16)
            __syncthreads();                                 // O staged

            gemm1(a_lane, g_wfrag + (4*l + 3) * 4096 + wfoff, mw, d);
            __syncthreads();                                 // all O reads done
            if (l < 3) {
                epi_hnew(d, smem, bo + l * 128, mw, nw, lane); // H_new (fp16)
            } else {
                float* ob = out + (size_t)bi * 8388608 + (size_t)t * 128;
                epi_out(d, ob, bo + l * 128, mw, nw, lane);
            }
        }
    }
}

extern "C" void kernel_launch(void* const* d_in, const int* in_sizes, int n_in,
                              void* d_out, int out_size)
{
    const float* x  = (const float*)d_in[0];
    const float* Wq = (const float*)d_in[1];
    const float* bq = (const float*)d_in[2];
    const float* Wk = (const float*)d_in[3];
    const float* bk = (const float*)d_in[4];
    const float* Wv = (const float*)d_in[5];
    const float* bv = (const float*)d_in[6];
    const float* Wo = (const float*)d_in[7];
    const float* bo = (const float*)d_in[8];
    float* out = (float*)d_out;

    const int NB = in_sizes[0] / (128 * TT * 128);   // batch (4)
    const int nseq = NB * TT;

    prep_w<<<17, 256>>>(Wq, Wk, Wv, Wo);

    cudaFuncSetAttribute(hattn_mma, cudaFuncAttributeMaxDynamicSharedMemorySize, SMEM_TOTAL);
    int grid = 152;                                  // GB300 SM count; 1 CTA/SM
    if (grid > nseq) grid = nseq;
    hattn_mma<<<grid, NTHREADS, SMEM_TOTAL>>>(x, bq, bk, bv, bo, out, nseq);
}

// round 17
// speedup vs baseline: 2.2218x; 1.0668x over previous
#include <cuda_runtime.h>
#include <cuda_fp16.h>
#include <cstdint>

// HarmonicAwaredAttention via warp-level HMMA (mma.sync, arch-agnostic PTX).
// R17: 2 CTAs/SM x 256 threads (cross-CTA phase overlap), warp grid 2(M)x4(N)
//      tile 64x32 (GEMM L1 bytes -25%), Q overlays H (smem 104KB), STS.128
//      staging, 2-phase attention (regs<128). All GEMMs single-term fp16.

#define TT 512
#define NTHREADS 256
#define LDH_B  272            // fp16 row stride in bytes (136 elems)
#define LDKV_B 272            // K/V fp16 row stride in bytes

// smem byte offsets
#define HHI_OFF 0              // fp16 H (Q overlay after QKV gemms; O after attn)
#define KS_OFF  34816          // fp16 K
#define VS_OFF  69632          // fp16 V
#define SMEM_TOTAL 104448

// weights, fragment-linear uint2 (fp16): [gemm][ks 0..7][j 0..15][lane 0..31]
__device__ __align__(16) uint2 g_wfrag[16 * 4096];
__device__ float g_pe[128 * 128];     // g_pe[c*128 + f]

__device__ __forceinline__ uint32_t smem_u32(const void* p) {
    uint32_t a;
    asm("{ .reg .u64 t; cvta.to.shared.u64 t, %1; cvt.u32.u64 %0, t; }" : "=r"(a) : "l"(p));
    return a;
}

#define LDSM(r, addr) \
    asm volatile("ldmatrix.sync.aligned.m8n8.x4.shared.b16 {%0,%1,%2,%3}, [%4];" \
        : "=r"((r)[0]), "=r"((r)[1]), "=r"((r)[2]), "=r"((r)[3]) : "r"(addr))

#define MMA(dp, a, bx, by) \
    asm volatile("mma.sync.aligned.m16n8k16.row.col.f32.f16.f16.f32 " \
        "{%0,%1,%2,%3},{%4,%5,%6,%7},{%8,%9},{%0,%1,%2,%3};" \
        : "+f"((dp)[0]), "+f"((dp)[1]), "+f"((dp)[2]), "+f"((dp)[3]) \
        : "r"((a)[0]), "r"((a)[1]), "r"((a)[2]), "r"((a)[3]), "r"(bx), "r"(by))

// K/V/Q fp16 chunk layout: byte(r, C) = r*272 + (C>>5)*32 + ((i&1)<<7)+((i>>1)<<4)
// + (C&7)*2, i = (C&31)>>3. Epilogue STS.32 and attention LDS.128 wavefront-optimal.

// ---------------- prologue: fragment-pack weights + PE table ----------------
__global__ void prep_w(const float* __restrict__ Wq, const float* __restrict__ Wk,
                       const float* __restrict__ Wv, const float* __restrict__ Wo)
{
    int g = blockIdx.x;
    if (g == 16) {   // PE table
        for (int idx = threadIdx.x; idx < 128 * 128; idx += blockDim.x) {
            int c = idx >> 7, f = idx & 127;
            float e     = (float)(c & ~1) * (1.0f / 128.0f);
            float denom = exp2f(e * 13.287712379549449f);   // 10000^(i/128)
            float ang   = (float)f / denom;
            g_pe[c * 128 + f] = (c & 1) ? cosf(ang) : sinf(ang);
        }
        return;
    }
    int l = g >> 2, m = g & 3;
    const float* src = (m == 0 ? Wk : m == 1 ? Wv : m == 2 ? Wq : Wo) + l * 16384;
    for (int e = threadIdx.x; e < 4096; e += blockDim.x) {
        int lane = e & 31, j = (e >> 5) & 15, ks = e >> 9;
        int n  = 8 * j + (lane >> 2);
        int k0 = 16 * ks + 2 * (lane & 3);
        float w00 = src[k0 * 128 + n],       w01 = src[(k0 + 1) * 128 + n];
        float w10 = src[(k0 + 8) * 128 + n], w11 = src[(k0 + 9) * 128 + n];
        __half2 h0 = __floats2half2_rn(w00, w01);
        __half2 h1 = __floats2half2_rn(w10, w11);
        uint2 o;
        o.x = *(uint32_t*)&h0;
        o.y = *(uint32_t*)&h1;
        g_wfrag[g * 4096 + e] = o;
    }
}

// ---- single-term GEMM: warp (mw in 0..1, nw in 0..3) tile 64x32 ----
// d[mt*4+jj][4]: mt 0..3 (16-row tiles), jj 0..3 (8-col tiles).
__device__ __forceinline__ void gemm1(uint32_t a_lane, const uint2* __restrict__ wf,
                                      int mw, float (*d)[4])
{
#pragma unroll
    for (int i = 0; i < 16; i++) { d[i][0] = 0.f; d[i][1] = 0.f; d[i][2] = 0.f; d[i][3] = 0.f; }

    const uint32_t a_row = (uint32_t)(mw * 64) * LDH_B;

    uint32_t ah[2][4];
    LDSM(ah[0], a_lane + a_row);           // stage (ks=0, mt=0)

    uint2 b[4];
#pragma unroll
    for (int jj = 0; jj < 4; jj++) b[jj] = __ldg(wf + jj * 32);

#pragma unroll
    for (int ks = 0; ks < 8; ks++) {
        uint2 nb[4];
        {   // full-ks-ahead B prefetch (wraps at end; harmless reload)
            const uint2* p = wf + (((ks + 1) & 7) * 512);
#pragma unroll
            for (int jj = 0; jj < 4; jj++) nb[jj] = __ldg(p + jj * 32);
        }
#pragma unroll
        for (int mt = 0; mt < 4; mt++) {
            if (!(ks == 7 && mt == 3)) {   // prefetch next A stage
                const int nks = (mt == 3) ? ks + 1 : ks;
                const int nmt = (mt + 1) & 3;
                LDSM(ah[(mt + 1) & 1],
                     a_lane + a_row + (uint32_t)(nmt * 16) * LDH_B + (uint32_t)nks * 32);
            }
#pragma unroll
            for (int jj = 0; jj < 4; jj++)
                MMA(d[mt * 4 + jj], ah[mt & 1], b[jj].x, b[jj].y);
        }
#pragma unroll
        for (int jj = 0; jj < 4; jj++) b[jj] = nb[jj];
    }
}

// D + bias -> fp16 smem (chunk-interleaved layout). STS.32 conflict-light.
__device__ __forceinline__ void epi_h16(float (*d)[4], unsigned char* vb,
                                        const float* bias, int mw, int nw, int lane)
{
    int rq = lane >> 2, cq = 2 * (lane & 3);
#pragma unroll
    for (int jj = 0; jj < 4; jj++) {
        int c = 32 * nw + 8 * jj + cq;
        float b0 = __ldg(&bias[c]), b1 = __ldg(&bias[c + 1]);
        int colpart = nw * 32 + ((jj & 1) << 7) + ((jj >> 1) << 4) + cq * 2;
#pragma unroll
        for (int mt = 0; mt < 4; mt++) {
            int r0 = 64 * mw + 16 * mt + rq;
            __half2 h0 = __floats2half2_rn(d[mt*4+jj][0] + b0, d[mt*4+jj][1] + b1);
            __half2 h1 = __floats2half2_rn(d[mt*4+jj][2] + b0, d[mt*4+jj][3] + b1);
            *(uint32_t*)(vb + r0 * LDKV_B + colpart)       = *(uint32_t*)&h0;
            *(uint32_t*)(vb + (r0 + 8) * LDKV_B + colpart) = *(uint32_t*)&h1;
        }
    }
}

// D + bias -> plain fp16 H buffer (row-linear, LDSM layout)
__device__ __forceinline__ void epi_hnew(float (*d)[4], unsigned char* sm,
                                         const float* bias, int mw, int nw, int lane)
{
    int rq = lane >> 2, cq = 2 * (lane & 3);
#pragma unroll
    for (int jj = 0; jj < 4; jj++) {
        int c = 32 * nw + 8 * jj + cq;
        float b0 = __ldg(&bias[c]), b1 = __ldg(&bias[c + 1]);
#pragma unroll
        for (int mt = 0; mt < 4; mt++) {
            int r0 = 64 * mw + 16 * mt + rq;
#pragma unroll
            for (int hh = 0; hh < 2; hh++) {
                int r = r0 + 8 * hh;
                float v0 = d[mt*4+jj][2*hh]     + b0;
                float v1 = d[mt*4+jj][2*hh + 1] + b1;
                __half2 hi2 = __floats2half2_rn(v0, v1);
                *(uint32_t*)(sm + HHI_OFF + r * LDH_B + c * 2) = *(uint32_t*)&hi2;
            }
        }
    }
}

// D + bias -> gmem out (transposed: out[c][r], channel stride 65536)
__device__ __forceinline__ void epi_out(float (*d)[4], float* ob, const float* bias,
                                        int mw, int nw, int lane)
{
    int rq = lane >> 2, cq = 2 * (lane & 3);
#pragma unroll
    for (int jj = 0; jj < 4; jj++) {
        int c = 32 * nw + 8 * jj + cq;
        float b0 = __ldg(&bias[c]), b1 = __ldg(&bias[c + 1]);
#pragma unroll
        for (int mt = 0; mt < 4; mt++) {
            int r0 = 64 * mw + 16 * mt + rq;
            ob[(size_t)c * 65536 + r0]           = d[mt*4+jj][0] + b0;
            ob[(size_t)(c + 1) * 65536 + r0]     = d[mt*4+jj][1] + b1;
            ob[(size_t)c * 65536 + r0 + 8]       = d[mt*4+jj][2] + b0;
            ob[(size_t)(c + 1) * 65536 + r0 + 8] = d[mt*4+jj][3] + b1;
        }
    }
}

// 64 fp32 vals (one row, cols c0..c0+63) -> fp16 row-linear H buffer, STS.128
__device__ __forceinline__ void stage64(const float* v, unsigned char* sm,
                                        int row, int c0)
{
#pragma unroll
    for (int i = 0; i < 8; i++) {
        __half2 p0 = __floats2half2_rn(v[8*i],     v[8*i + 1]);
        __half2 p1 = __floats2half2_rn(v[8*i + 2], v[8*i + 3]);
        __half2 p2 = __floats2half2_rn(v[8*i + 4], v[8*i + 5]);
        __half2 p3 = __floats2half2_rn(v[8*i + 6], v[8*i + 7]);
        uint4 pk;
        pk.x = *(uint32_t*)&p0;  pk.y = *(uint32_t*)&p1;
        pk.z = *(uint32_t*)&p2;  pk.w = *(uint32_t*)&p3;
        *(uint4*)(sm + HHI_OFF + row * LDH_B + (c0 + 8 * i) * 2) = pk;
    }
}

extern __shared__ unsigned char smem[];

__global__ void __launch_bounds__(NTHREADS, 2)
hattn_mma(const float* __restrict__ x,
          const float* __restrict__ bq, const float* __restrict__ bk,
          const float* __restrict__ bv, const float* __restrict__ bo,
          float* __restrict__ out, int nseq)
{
    const int tid = threadIdx.x;
    const int w = tid >> 5, lane = tid & 31;
    const int mw = w & 1, nw = w >> 1;          // warp grid 2(M) x 4(N)

    unsigned char* Hb = smem + HHI_OFF;         // H / Q-overlay / O
    unsigned char* Kh = smem + KS_OFF;
    unsigned char* Vh = smem + VS_OFF;

    const uint32_t smbase = smem_u32(smem);
    const uint32_t a_lane = smbase + HHI_OFF + (lane & 15) * LDH_B + (lane >> 4) * 16;

    const int wfoff = (4 * nw) * 32 + lane;     // B fragment base offset for this warp

    // attention / staging mapping: thread owns (row, head h) -> 64 cols
    const int row = tid >> 1;
    const int h   = tid & 1;
    const int c0  = 64 * h;

    const int deltas[11] = {-124, -111, -96, -76, -48, 0, 48, 76, 96, 111, 124};
    float d[16][4];

    // persistent: each block walks sequences n = bid, bid+grid, ...
    for (int n = blockIdx.x; n < nseq; n += gridDim.x) {
        const int bi = n >> 9;                   // n / TT
        const int t  = n & (TT - 1);

        // ---- stage H = x + PE (plain fp16, row-linear) ----
        {
            const float* xb = x + (size_t)bi * 8388608 + (size_t)t * 128;
            float v[64];
#pragma unroll
            for (int c = 0; c < 64; c++)
                v[c] = xb[(size_t)(c0 + c) * 65536 + row] + g_pe[(c0 + c) * 128 + row];
            stage64(v, smem, row, c0);
        }

#pragma unroll 1
        for (int l = 0; l < 4; l++) {
            __syncthreads();                                 // (A) H staged/visible

            gemm1(a_lane, g_wfrag + (4*l + 0) * 4096 + wfoff, mw, d);
            epi_h16(d, Kh, bk + l * 128, mw, nw, lane);
            gemm1(a_lane, g_wfrag + (4*l + 1) * 4096 + wfoff, mw, d);
            epi_h16(d, Vh, bv + l * 128, mw, nw, lane);
            gemm1(a_lane, g_wfrag + (4*l + 2) * 4096 + wfoff, mw, d);
            __syncthreads();                                 // (B) all H reads done
            epi_h16(d, Hb, bq + l * 128, mw, nw, lane);      // Q overlays H region
            __syncthreads();                                 // (C) Q/K/V visible

            // ---- sparse harmonic attention: thread owns (row, head h) ----
            float o[64];
            {
                // phase 1: scores (q live, o not yet)
                float sv[11];
                {
                    float q[64];
                    {
                        const unsigned char* qb = Hb + row * LDKV_B;
#pragma unroll
                        for (int g = 0; g < 2; g++)
#pragma unroll
                            for (int i = 0; i < 4; i++) {
                                uint4 raw = *(const uint4*)(qb + (2*h + g) * 32 +
                                            ((i & 1) << 7) + ((i >> 1) << 4));
                                const __half2* hp = (const __half2*)&raw;
#pragma unroll
                                for (int tp = 0; tp < 4; tp++) {
                                    float2 f = __half22float2(hp[tp]);
                                    q[g*32 + 8*i + 2*tp]     = f.x;
                                    q[g*32 + 8*i + 2*tp + 1] = f.y;
                                }
                            }
                    }
#pragma unroll
                    for (int dd = 0; dd < 11; dd++) {
                        int j = row + deltas[dd];
                        bool valid = (unsigned)j < 128u;
                        float a = 0.f;
                        if (valid) {
                            const unsigned char* kb = Kh + j * LDKV_B;
#pragma unroll
                            for (int g = 0; g < 2; g++)
#pragma unroll
                                for (int i = 0; i < 4; i++) {
                                    uint4 raw = *(const uint4*)(kb + (2*h + g) * 32 +
                                                ((i & 1) << 7) + ((i >> 1) << 4));
                                    const __half2* hp = (const __half2*)&raw;
#pragma unroll
                                    for (int tp = 0; tp < 4; tp++) {
                                        float2 f = __half22float2(hp[tp]);
                                        a = fmaf(q[g*32 + 8*i + 2*tp],     f.x, a);
                                        a = fmaf(q[g*32 + 8*i + 2*tp + 1], f.y, a);
                                    }
                                }
                        }
                        sv[dd] = valid ? a * 0.125f : -1e30f;   // 1/sqrt(64)
                    }
                }
                float m = sv[0];
#pragma unroll
                for (int dd = 1; dd < 11; dd++) m = fmaxf(m, sv[dd]);
                float sum = 0.f;
#pragma unroll
                for (int dd = 0; dd < 11; dd++) {
                    float e = __expf(sv[dd] - m);
                    sv[dd] = e;
                    sum += e;
                }
                float inv = __fdividef(1.f, sum);

                // phase 2: output accumulation (q dead, o live)
#pragma unroll
                for (int i = 0; i < 64; i++) o[i] = 0.f;
#pragma unroll
                for (int dd = 0; dd < 11; dd++) {
                    int j = row + deltas[dd];
                    if ((unsigned)j < 128u) {
                        float wj = sv[dd] * inv;
                        const unsigned char* vb = Vh + j * LDKV_B;
#pragma unroll
                        for (int g = 0; g < 2; g++)
#pragma unroll
                            for (int i = 0; i < 4; i++) {
                                uint4 raw = *(const uint4*)(vb + (2*h + g) * 32 +
                                            ((i & 1) << 7) + ((i >> 1) << 4));
                                const __half2* hp = (const __half2*)&raw;
#pragma unroll
                                for (int tp = 0; tp < 4; tp++) {
                                    float2 f = __half22float2(hp[tp]);
                                    o[g*32 + 8*i + 2*tp]     = fmaf(wj, f.x, o[g*32 + 8*i + 2*tp]);
                                    o[g*32 + 8*i + 2*tp + 1] = fmaf(wj, f.y, o[g*32 + 8*i + 2*tp + 1]);
                                }
                            }
                    }
                }
            }
            __syncthreads();                                 // (D) all Q reads done
            stage64(o, smem, row, c0);                       // O -> H region (row-linear)
            __syncthreads();                                 // (E) O staged

            gemm1(a_lane, g_wfrag + (4*l + 3) * 4096 + wfoff, mw, d);
            __syncthreads();                                 // (F) all O reads done
            if (l < 3) {
                epi_hnew(d, smem, bo + l * 128, mw, nw, lane); // H_new (fp16)
            } else {
                float* ob = out + (size_t)bi * 8388608 + (size_t)t * 128;
                epi_out(d, ob, bo + l * 128, mw, nw, lane);
            }
        }
    }
}

extern "C" void kernel_launch(void* const* d_in, const int* in_sizes, int n_in,
                              void* d_out, int out_size)
{
    const float* x  = (const float*)d_in[0];
    const float* Wq = (const float*)d_in[1];
    const float* bq = (const float*)d_in[2];
    const float* Wk = (const float*)d_in[3];
    const float* bk = (const float*)d_in[4];
    const float* Wv = (const float*)d_in[5];
    const float* bv = (const float*)d_in[6];
    const float* Wo = (const float*)d_in[7];
    const float* bo = (const float*)d_in[8];
    float* out = (float*)d_out;

    const int NB = in_sizes[0] / (128 * TT * 128);   // batch (4)
    const int nseq = NB * TT;

    prep_w<<<17, 256>>>(Wq, Wk, Wv, Wo);

    cudaFuncSetAttribute(hattn_mma, cudaFuncAttributeMaxDynamicSharedMemorySize, SMEM_TOTAL);
    int grid = 304;                                  // 152 SMs x 2 CTAs
    if (grid > nseq) grid = nseq;
    hattn_mma<<<grid, NTHREADS, SMEM_TOTAL>>>(x, bq, bk, bv, bo, out, nseq);
}